// round 6
// baseline (speedup 1.0000x reference)
#include <cuda_runtime.h>
#include <cuda_bf16.h>
#include <cstdint>

typedef unsigned long long ull;

#define CDIM    256
#define HWDIM   1024
#define N_ROWS  32768
#define KCODES  1024

#define QUANT_OFF 1
#define PERP_OFF  8388609
#define ENC_OFF   8388610

#define DELTA   0.0625f

// ---------------- scratch ----------------
__device__ float          g_Xt[N_ROWS * CDIM];
__device__ __nv_bfloat16  g_Xh[N_ROWS * CDIM];
__device__ __nv_bfloat16  g_Xl[N_ROWS * CDIM];
__device__ __nv_bfloat16  g_Eh[KCODES * CDIM];
__device__ __nv_bfloat16  g_El[KCODES * CDIM];
__device__ float          g_xx[N_ROWS];
__device__ float          g_ee[KCODES];
__device__ ull            g_pKey[N_ROWS * 32];  // per (row, 32-col segment) top1
__device__ float          g_pS2[N_ROWS * 32];   // per-segment runner-up score
__device__ int            g_rowIdx[N_ROWS];
__device__ int            g_rescueRows[N_ROWS];
__device__ int            g_nRescue;
__device__ unsigned int   g_counts[KCODES];
__device__ float          g_kldSum;
__device__ float          g_elatSum;

// ---------------- helpers ----------------
__device__ __forceinline__ uint32_t smem_u32(const void* p) {
    uint32_t a;
    asm("{ .reg .u64 t; cvta.to.shared.u64 t, %1; cvt.u32.u64 %0, t; }" : "=r"(a) : "l"(p));
    return a;
}
__device__ __forceinline__ void cp16(uint32_t dst, const void* src) {
    asm volatile("cp.async.cg.shared.global [%0], [%1], 16;" :: "r"(dst), "l"(src));
}
#define CP_COMMIT() asm volatile("cp.async.commit_group;" ::: "memory")
#define CP_WAIT1()  asm volatile("cp.async.wait_group 1;" ::: "memory")
#define CP_WAIT0()  asm volatile("cp.async.wait_group 0;" ::: "memory")

__device__ __forceinline__ void ldsm4(uint32_t* r, uint32_t a) {
    asm volatile("ldmatrix.sync.aligned.m8n8.x4.shared.b16 {%0,%1,%2,%3}, [%4];"
                 : "=r"(r[0]), "=r"(r[1]), "=r"(r[2]), "=r"(r[3]) : "r"(a));
}
__device__ __forceinline__ void ldsm2(uint32_t* r, uint32_t a) {
    asm volatile("ldmatrix.sync.aligned.m8n8.x2.shared.b16 {%0,%1}, [%2];"
                 : "=r"(r[0]), "=r"(r[1]) : "r"(a));
}
__device__ __forceinline__ void mma_bf16(float* c, uint32_t a0, uint32_t a1,
                                         uint32_t a2, uint32_t a3,
                                         uint32_t b0, uint32_t b1) {
    asm volatile("mma.sync.aligned.m16n8k16.row.col.f32.bf16.bf16.f32 "
                 "{%0,%1,%2,%3}, {%4,%5,%6,%7}, {%8,%9}, {%0,%1,%2,%3};"
                 : "+f"(c[0]), "+f"(c[1]), "+f"(c[2]), "+f"(c[3])
                 : "r"(a0), "r"(a1), "r"(a2), "r"(a3), "r"(b0), "r"(b1));
}

__device__ __forceinline__ ull packKey(float s, int idx) {
    unsigned u = __float_as_uint(s);
    u = (u & 0x80000000u) ? ~u : (u | 0x80000000u);
    return ((ull)u << 32) | (unsigned)(1023 - idx);
}
__device__ __forceinline__ float decodeKey(ull k) {
    unsigned u = (unsigned)(k >> 32);
    unsigned v = (u & 0x80000000u) ? (u & 0x7FFFFFFFu) : ~u;
    return __uint_as_float(v);
}

// ---------------- init ----------------
__global__ void initKernel() {
    int t = blockIdx.x * blockDim.x + threadIdx.x;
    if (t < KCODES) g_counts[t] = 0u;
    if (t == 0) { g_kldSum = 0.0f; g_elatSum = 0.0f; g_nRescue = 0; }
}

// ---------------- NCHW -> [N,C] transpose + bf16 hi/lo split ----------------
__global__ void transConvKernel(const float* __restrict__ in) {
    __shared__ float tile[32][33];
    int b   = blockIdx.z;
    int hw0 = blockIdx.x << 5;
    int c0  = blockIdx.y << 5;
    const float* p = in + (size_t)b * CDIM * HWDIM;
#pragma unroll
    for (int j = 0; j < 4; j++) {
        int cl = threadIdx.y + (j << 3);
        tile[cl][threadIdx.x] = p[(size_t)(c0 + cl) * HWDIM + hw0 + threadIdx.x];
    }
    __syncthreads();
#pragma unroll
    for (int j = 0; j < 4; j++) {
        int hwl = threadIdx.y + (j << 3);
        size_t o = (size_t)(b * HWDIM + hw0 + hwl) * CDIM + c0 + threadIdx.x;
        float v = tile[threadIdx.x][hwl];
        g_Xt[o] = v;
        __nv_bfloat16 h = __float2bfloat16_rn(v);
        g_Xh[o] = h;
        g_Xl[o] = __float2bfloat16_rn(v - __bfloat162float(h));
    }
}

// ---------------- row sum-of-squares ----------------
__global__ void sumsqXt() {
    int gw   = (blockIdx.x * blockDim.x + threadIdx.x) >> 5;
    int lane = threadIdx.x & 31;
    if (gw >= N_ROWS) return;
    const float* p = g_Xt + (size_t)gw * CDIM;
    float4 a = *(const float4*)(p + (lane << 2));
    float4 b = *(const float4*)(p + 128 + (lane << 2));
    float s = a.x*a.x + a.y*a.y + a.z*a.z + a.w*a.w
            + b.x*b.x + b.y*b.y + b.z*b.z + b.w*b.w;
#pragma unroll
    for (int off = 16; off; off >>= 1) s += __shfl_xor_sync(0xFFFFFFFFu, s, off);
    if (lane == 0) g_xx[gw] = s;
}
__global__ void sumsqE(const float* __restrict__ E) {
    int gw   = (blockIdx.x * blockDim.x + threadIdx.x) >> 5;
    int lane = threadIdx.x & 31;
    if (gw >= KCODES) return;
    const float* p = E + (size_t)gw * CDIM;
    float4 a = *(const float4*)(p + (lane << 2));
    float4 b = *(const float4*)(p + 128 + (lane << 2));
    float s = a.x*a.x + a.y*a.y + a.z*a.z + a.w*a.w
            + b.x*b.x + b.y*b.y + b.z*b.z + b.w*b.w;
#pragma unroll
    for (int off = 16; off; off >>= 1) s += __shfl_xor_sync(0xFFFFFFFFu, s, off);
    if (lane == 0) g_ee[gw] = s;
}

// ---------------- E bf16 hi/lo split ----------------
__global__ void convEKernel(const float* __restrict__ E) {
    size_t o = (size_t)blockIdx.x * CDIM + threadIdx.x;
    float v = E[o];
    __nv_bfloat16 h = __float2bfloat16_rn(v);
    g_Eh[o] = h;
    g_El[o] = __float2bfloat16_rn(v - __bfloat162float(h));
}

// ---------------- HMMA bf16x3 GEMM + fused top2/enc/kld epilogue ----------
// CTA: 128 rows (blockIdx.y) x 128 codes (blockIdx.x). 8 warps, 2x4, warp 64x32.
// Virtual K=768: chunks 0-3 Xh*Eh, 4-7 Xh*El, 8-11 Xl*Eh; 64-K double-buffered.
#define STR_B   144                 // 72 bf16 padded row (bytes)
#define A_BYTES (128 * STR_B)       // 18432
#define STAGE_B (2 * A_BYTES)       // 36864 (A + B per stage)
#define SMEM_DYN (2 * STAGE_B)      // 73728
__global__ __launch_bounds__(256)
void gemmKernel(const float* __restrict__ G, float* __restrict__ enc) {
    extern __shared__ char dsm[];
    const uint32_t sb = smem_u32(dsm);

    const int tid  = threadIdx.x;
    const int warp = tid >> 5;
    const int lane = tid & 31;
    const int wm   = warp >> 2;          // 0..1
    const int wn   = warp & 3;           // 0..3
    const int m0   = blockIdx.y << 7;
    const int j0   = blockIdx.x << 7;

    float acc[4][4][4];
#pragma unroll
    for (int i = 0; i < 4; i++)
#pragma unroll
        for (int j = 0; j < 4; j++)
#pragma unroll
            for (int k = 0; k < 4; k++) acc[i][j][k] = 0.0f;

    // chunk loader: 4 cp.async of 16B for A, 4 for B
    auto loadChunk = [&](int c, int stage) {
        const __nv_bfloat16* Asrc = (c < 8) ? g_Xh : g_Xl;
        const __nv_bfloat16* Bsrc = (c < 4 || c >= 8) ? g_Eh : g_El;
        const int kb = (c & 3) << 6;
        const uint32_t aBase = sb + (uint32_t)stage * STAGE_B;
        const uint32_t bBase = aBase + A_BYTES;
#pragma unroll
        for (int t = 0; t < 4; t++) {
            int id = tid + (t << 8);
            int r = id >> 3, c16 = id & 7;
            cp16(aBase + r * STR_B + (c16 << 4),
                 Asrc + (size_t)(m0 + r) * CDIM + kb + (c16 << 3));
        }
#pragma unroll
        for (int t = 0; t < 4; t++) {
            int id = tid + (t << 8);
            int r = id >> 3, c16 = id & 7;
            cp16(bBase + r * STR_B + (c16 << 4),
                 Bsrc + (size_t)(j0 + r) * CDIM + kb + (c16 << 3));
        }
        CP_COMMIT();
    };

    loadChunk(0, 0);

#pragma unroll 1
    for (int c = 0; c < 12; c++) {
        if (c + 1 < 12) loadChunk(c + 1, (c + 1) & 1);
        if (c + 1 < 12) { CP_WAIT1(); } else { CP_WAIT0(); }
        __syncthreads();

        const uint32_t aBase = sb + (uint32_t)(c & 1) * STAGE_B;
        const uint32_t bBase = aBase + A_BYTES;
#pragma unroll
        for (int ks = 0; ks < 4; ks++) {
            uint32_t bfr[4][2];
#pragma unroll
            for (int nf = 0; nf < 4; nf++) {
                uint32_t addr = bBase
                    + (uint32_t)((wn << 5) + (nf << 3) + (lane & 7)) * STR_B
                    + (uint32_t)(ks << 5) + (uint32_t)(((lane >> 3) & 1) << 4);
                ldsm2(bfr[nf], addr);
            }
#pragma unroll
            for (int mf = 0; mf < 4; mf++) {
                uint32_t afr[4];
                uint32_t addr = aBase
                    + (uint32_t)((wm << 6) + (mf << 4) + (lane & 15)) * STR_B
                    + (uint32_t)(ks << 5) + (uint32_t)((lane >> 4) << 4);
                ldsm4(afr, addr);
#pragma unroll
                for (int nf = 0; nf < 4; nf++)
                    mma_bf16(acc[mf][nf], afr[0], afr[1], afr[2], afr[3],
                             bfr[nf][0], bfr[nf][1]);
            }
        }
        __syncthreads();
    }

    // -------- epilogue: fragment layout c0=(r,2q) c1=(r,2q+1) c2=(r+8,..) --------
    const int quad = lane >> 2;
    const int q    = lane & 3;
    float kld = 0.0f;
    const float2 z2 = make_float2(0.f, 0.f);

#pragma unroll
    for (int mf = 0; mf < 4; mf++) {
#pragma unroll
        for (int half = 0; half < 2; half++) {
            const int row = m0 + (wm << 6) + (mf << 4) + quad + (half << 3);
            const float xxr = g_xx[row];
            ull   k1 = 0ull;
            float s1 = -3.0e38f, s2 = -3.0e38f;
#pragma unroll
            for (int nf = 0; nf < 4; nf++) {
                const int col = j0 + (wn << 5) + (nf << 3) + (q << 1);
                float c0 = acc[mf][nf][half << 1];
                float c1 = acc[mf][nf][(half << 1) + 1];
                float2 g2 = *(const float2*)(G + (size_t)row * KCODES + col);
                float2 e2 = *(const float2*)(g_ee + col);

                float d0 = (xxr + e2.x) - 2.0f * c0;
                float d1 = (xxr + e2.y) - 2.0f * c1;
                if (d0 < 85.0f) {
                    float pr = 1.0f / (1.0f + expf(d0));
                    kld += pr * logf(fmaxf(pr, 1e-8f));
                }
                if (d1 < 85.0f) {
                    float pr = 1.0f / (1.0f + expf(d1));
                    kld += pr * logf(fmaxf(pr, 1e-8f));
                }
                float s0 = g2.x - d0;
                float s1v = g2.y - d1;
                ull k0 = packKey(s0, col);
                if (k0 > k1) { s2 = s1; k1 = k0; s1 = s0; } else { s2 = fmaxf(s2, s0); }
                ull kk1 = packKey(s1v, col + 1);
                if (kk1 > k1) { s2 = s1; k1 = kk1; s1 = s1v; } else { s2 = fmaxf(s2, s1v); }

                *(float2*)(enc + (size_t)row * KCODES + col) = z2;
            }
            // merge across the 4 quad lanes (xor 1, 2 stay within quad)
#pragma unroll
            for (int x = 1; x <= 2; x <<= 1) {
                ull   ok  = __shfl_xor_sync(0xFFFFFFFFu, k1, x);
                float os1 = __shfl_xor_sync(0xFFFFFFFFu, s1, x);
                float os2 = __shfl_xor_sync(0xFFFFFFFFu, s2, x);
                if (ok > k1) { s2 = fmaxf(fmaxf(s2, os2), s1); k1 = ok; s1 = os1; }
                else         { s2 = fmaxf(fmaxf(s2, os2), os1); }
            }
            if (q == 0) {
                // FIX (R6): one slot per (row, 32-col warp segment).
                // R5 raced: 4 wn-warps shared a slot, dropping 3/4 of candidates.
                int slot = (row << 5) + ((int)blockIdx.x << 2) + wn;
                g_pKey[slot] = k1;
                g_pS2[slot]  = s2;
            }
        }
    }

#pragma unroll
    for (int off = 16; off; off >>= 1) kld += __shfl_down_sync(0xFFFFFFFFu, kld, off);
    if (lane == 0 && kld != 0.0f) atomicAdd(&g_kldSum, kld);
}

// ---------------- merge partials -> idx or rescue flag ----------------
__global__ void mergeKernel() {
    int row = blockIdx.x * blockDim.x + threadIdx.x;
    if (row >= N_ROWS) return;
    ull best = 0ull;
#pragma unroll
    for (int t = 0; t < 32; t++) best = max(best, g_pKey[(row << 5) + t]);
    float runner = -3.0e38f;
#pragma unroll
    for (int t = 0; t < 32; t++) {
        ull k = g_pKey[(row << 5) + t];
        if (k != best) runner = fmaxf(runner, decodeKey(k));
        runner = fmaxf(runner, g_pS2[(row << 5) + t]);
    }
    float margin = decodeKey(best) - runner;
    if (margin < DELTA) {
        int p = atomicAdd(&g_nRescue, 1);
        g_rescueRows[p] = row;
    } else {
        g_rowIdx[row] = 1023 - (int)(unsigned)(best & 0xFFFFFFFFull);
    }
}

// ---------------- fp32 rescue for tight rows ----------------
__global__ __launch_bounds__(256)
void rescueKernel(const float* __restrict__ E, const float* __restrict__ G) {
    __shared__ float sx[CDIM];
    __shared__ ull   rk[8];
    const int tid = threadIdx.x;
    const int nR  = g_nRescue;
    for (int i = blockIdx.x; i < nR; i += gridDim.x) {
        int row = g_rescueRows[i];
        sx[tid] = g_Xt[(size_t)row * CDIM + tid];
        __syncthreads();
        float xxr = g_xx[row];
        ull key = 0ull;
#pragma unroll 1
        for (int cc = 0; cc < 4; cc++) {
            int code = tid + (cc << 8);
            const float* e = E + (size_t)code * CDIM;
            float acc = 0.0f;
#pragma unroll 8
            for (int k = 0; k < CDIM; k++) acc = fmaf(sx[k], e[k], acc);
            float d = (xxr + g_ee[code]) - 2.0f * acc;
            float s = G[(size_t)row * KCODES + code] - d;
            ull kk = packKey(s, code);
            key = max(key, kk);
        }
#pragma unroll
        for (int off = 16; off; off >>= 1)
            key = max(key, __shfl_down_sync(0xFFFFFFFFu, key, off));
        if ((tid & 31) == 0) rk[tid >> 5] = key;
        __syncthreads();
        if (tid == 0) {
            ull b = rk[0];
#pragma unroll
            for (int w = 1; w < 8; w++) b = max(b, rk[w]);
            g_rowIdx[row] = 1023 - (int)(unsigned)(b & 0xFFFFFFFFull);
        }
        __syncthreads();
    }
}

// ---------------- finish: one-hot scatter, quantized NCHW, e_latent, hist ----
__global__ __launch_bounds__(256)
void finishKernel(const float* __restrict__ E, float* __restrict__ out) {
    __shared__ int   sIdx[32];
    __shared__ float sQ[32 * 257];
    __shared__ float r2[8];

    const int n0  = blockIdx.x << 5;
    const int tid = threadIdx.x;

    if (tid < 32) {
        int idx = g_rowIdx[n0 + tid];
        sIdx[tid] = idx;
        out[ENC_OFF + (size_t)(n0 + tid) * KCODES + idx] = 1.0f;
        atomicAdd(&g_counts[idx], 1u);
    }
    __syncthreads();

    float accum = 0.0f;
    const int c = tid;
#pragma unroll 4
    for (int i = 0; i < 32; i++) {
        float v = E[(size_t)sIdx[i] * CDIM + c];
        float x = g_Xt[(size_t)(n0 + i) * CDIM + c];
        float dlt = v - x;
        accum += dlt * dlt;
        sQ[i * 257 + c] = v;
    }
    __syncthreads();

    const int b   = n0 >> 10;
    const int hw0 = n0 & 1023;
    float* qb = out + QUANT_OFF + (size_t)b * CDIM * HWDIM;
#pragma unroll 4
    for (int it = 0; it < 32; it++) {
        int f  = it * 256 + tid;
        int cc = f >> 5;
        int ii = f & 31;
        qb[(size_t)cc * HWDIM + hw0 + ii] = sQ[ii * 257 + cc];
    }

#pragma unroll
    for (int off = 16; off; off >>= 1) accum += __shfl_down_sync(0xFFFFFFFFu, accum, off);
    if ((tid & 31) == 0) r2[tid >> 5] = accum;
    __syncthreads();
    if (tid == 0) {
        float s = 0.0f;
#pragma unroll
        for (int w = 0; w < 8; w++) s += r2[w];
        atomicAdd(&g_elatSum, s);
    }
}

// ---------------- scalars ----------------
__global__ void lossKernel(float* __restrict__ out) {
    __shared__ float red[32];
    int t = threadIdx.x;
    float avg  = (float)g_counts[t] * (1.0f / 32768.0f);
    float term = avg * logf(avg + 1e-10f);
#pragma unroll
    for (int off = 16; off; off >>= 1) term += __shfl_down_sync(0xFFFFFFFFu, term, off);
    if ((t & 31) == 0) red[t >> 5] = term;
    __syncthreads();
    if (t < 32) {
        float v = red[t];
#pragma unroll
        for (int off = 16; off; off >>= 1) v += __shfl_down_sync(0xFFFFFFFFu, v, off);
        if (t == 0) {
            float perp = expf(-v);
            float eLat = g_elatSum * (1.0f / 8388608.0f);
            float kld  = g_kldSum * (1.0f / 32768.0f);
            float loss = 1.5f * (kld + eLat * (kld / fmaxf(eLat, 1e-8f)));
            out[0]        = loss;
            out[PERP_OFF] = perp;
        }
    }
}

// ---------------- launch ----------------
extern "C" void kernel_launch(void* const* d_in, const int* in_sizes, int n_in,
                              void* d_out, int out_size) {
    const float* inp = (const float*)d_in[0];
    const float* emb = (const float*)d_in[1];
    const float* gum = (const float*)d_in[2];
    float* out = (float*)d_out;
    float* enc = out + ENC_OFF;

    cudaFuncSetAttribute(gemmKernel, cudaFuncAttributeMaxDynamicSharedMemorySize, SMEM_DYN);

    initKernel<<<8, 256>>>();
    transConvKernel<<<dim3(32, 8, 32), dim3(32, 8)>>>(inp);
    sumsqXt<<<4096, 256>>>();
    sumsqE<<<128, 256>>>(emb);
    convEKernel<<<KCODES, 256>>>(emb);
    gemmKernel<<<dim3(KCODES / 128, N_ROWS / 128), 256, SMEM_DYN>>>(gum, enc);
    mergeKernel<<<128, 256>>>();
    rescueKernel<<<256, 256>>>(emb, gum);
    finishKernel<<<N_ROWS / 32, 256>>>(emb, out);
    lossKernel<<<1, 1024>>>(out);
}

// round 7
// speedup vs baseline: 1.3478x; 1.3478x over previous
#include <cuda_runtime.h>
#include <cuda_bf16.h>
#include <cstdint>

typedef unsigned long long ull;

#define CDIM    256
#define HWDIM   1024
#define N_ROWS  32768
#define KCODES  1024

#define QUANT_OFF 1
#define PERP_OFF  8388609
#define ENC_OFF   8388610

#define DELTA   0.012f

// ---------------- scratch ----------------
__device__ float          g_Xt[N_ROWS * CDIM];
__device__ __nv_bfloat16  g_Xh[N_ROWS * CDIM];
__device__ __nv_bfloat16  g_Xl[N_ROWS * CDIM];
__device__ __nv_bfloat16  g_Eh[KCODES * CDIM];
__device__ __nv_bfloat16  g_El[KCODES * CDIM];
__device__ float          g_xx[N_ROWS];
__device__ float          g_ee[KCODES];
__device__ ull            g_pKey[N_ROWS * 32];  // per (row, 32-col segment) top1
__device__ float          g_pS2[N_ROWS * 32];   // per-segment runner-up score
__device__ int            g_rowIdx[N_ROWS];
__device__ int            g_rescueRows[N_ROWS];
__device__ int            g_nRescue;
__device__ unsigned int   g_counts[KCODES];
__device__ float          g_kldSum;
__device__ float          g_elatSum;

// ---------------- helpers ----------------
__device__ __forceinline__ uint32_t smem_u32(const void* p) {
    uint32_t a;
    asm("{ .reg .u64 t; cvta.to.shared.u64 t, %1; cvt.u32.u64 %0, t; }" : "=r"(a) : "l"(p));
    return a;
}
__device__ __forceinline__ void cp16(uint32_t dst, const void* src) {
    asm volatile("cp.async.cg.shared.global [%0], [%1], 16;" :: "r"(dst), "l"(src));
}
#define CP_COMMIT() asm volatile("cp.async.commit_group;" ::: "memory")
#define CP_WAIT1()  asm volatile("cp.async.wait_group 1;" ::: "memory")
#define CP_WAIT0()  asm volatile("cp.async.wait_group 0;" ::: "memory")

__device__ __forceinline__ void ldsm4(uint32_t* r, uint32_t a) {
    asm volatile("ldmatrix.sync.aligned.m8n8.x4.shared.b16 {%0,%1,%2,%3}, [%4];"
                 : "=r"(r[0]), "=r"(r[1]), "=r"(r[2]), "=r"(r[3]) : "r"(a));
}
__device__ __forceinline__ void ldsm2(uint32_t* r, uint32_t a) {
    asm volatile("ldmatrix.sync.aligned.m8n8.x2.shared.b16 {%0,%1}, [%2];"
                 : "=r"(r[0]), "=r"(r[1]) : "r"(a));
}
__device__ __forceinline__ void mma_bf16(float* c, uint32_t a0, uint32_t a1,
                                         uint32_t a2, uint32_t a3,
                                         uint32_t b0, uint32_t b1) {
    asm volatile("mma.sync.aligned.m16n8k16.row.col.f32.bf16.bf16.f32 "
                 "{%0,%1,%2,%3}, {%4,%5,%6,%7}, {%8,%9}, {%0,%1,%2,%3};"
                 : "+f"(c[0]), "+f"(c[1]), "+f"(c[2]), "+f"(c[3])
                 : "r"(a0), "r"(a1), "r"(a2), "r"(a3), "r"(b0), "r"(b1));
}

__device__ __forceinline__ ull packKey(float s, int idx) {
    unsigned u = __float_as_uint(s);
    u = (u & 0x80000000u) ? ~u : (u | 0x80000000u);
    return ((ull)u << 32) | (unsigned)(1023 - idx);
}
__device__ __forceinline__ float decodeKey(ull k) {
    unsigned u = (unsigned)(k >> 32);
    unsigned v = (u & 0x80000000u) ? (u & 0x7FFFFFFFu) : ~u;
    return __uint_as_float(v);
}

// ---------------- init (also zeroes g_xx for the fused atomics) ----------------
__global__ void initKernel() {
    int t = blockIdx.x * blockDim.x + threadIdx.x;
    if (t < N_ROWS) g_xx[t] = 0.0f;
    if (t < KCODES) g_counts[t] = 0u;
    if (t == 0) { g_kldSum = 0.0f; g_elatSum = 0.0f; g_nRescue = 0; }
}

// ------- NCHW -> [N,C] transpose + bf16 hi/lo split + fused ||x||^2 ----------
__global__ void transConvKernel(const float* __restrict__ in) {
    __shared__ float tile[32][33];
    int b   = blockIdx.z;
    int hw0 = blockIdx.x << 5;
    int c0  = blockIdx.y << 5;
    const float* p = in + (size_t)b * CDIM * HWDIM;
#pragma unroll
    for (int j = 0; j < 4; j++) {
        int cl = threadIdx.y + (j << 3);
        tile[cl][threadIdx.x] = p[(size_t)(c0 + cl) * HWDIM + hw0 + threadIdx.x];
    }
    __syncthreads();
#pragma unroll
    for (int j = 0; j < 4; j++) {
        int hwl = threadIdx.y + (j << 3);
        int row = b * HWDIM + hw0 + hwl;
        size_t o = (size_t)row * CDIM + c0 + threadIdx.x;
        float v = tile[threadIdx.x][hwl];
        g_Xt[o] = v;
        __nv_bfloat16 h = __float2bfloat16_rn(v);
        g_Xh[o] = h;
        g_Xl[o] = __float2bfloat16_rn(v - __bfloat162float(h));
        // fused ||x||^2 partial: warp lanes span 32 c's of this row
        float s = v * v;
#pragma unroll
        for (int off = 16; off; off >>= 1) s += __shfl_xor_sync(0xFFFFFFFFu, s, off);
        if (threadIdx.x == 0) atomicAdd(&g_xx[row], s);
    }
}

// ---------------- E: sum-of-squares + bf16 hi/lo split (fused) ----------------
__global__ void sumsqEConv(const float* __restrict__ E) {
    int gw   = (blockIdx.x * blockDim.x + threadIdx.x) >> 5;
    int lane = threadIdx.x & 31;
    if (gw >= KCODES) return;
    const float* p = E + (size_t)gw * CDIM;
    float4 a = *(const float4*)(p + (lane << 2));
    float4 b = *(const float4*)(p + 128 + (lane << 2));
    float s = a.x*a.x + a.y*a.y + a.z*a.z + a.w*a.w
            + b.x*b.x + b.y*b.y + b.z*b.z + b.w*b.w;
#pragma unroll
    for (int off = 16; off; off >>= 1) s += __shfl_xor_sync(0xFFFFFFFFu, s, off);
    if (lane == 0) g_ee[gw] = s;

    float va[8] = { a.x, a.y, a.z, a.w, b.x, b.y, b.z, b.w };
#pragma unroll
    for (int i = 0; i < 8; i++) {
        size_t o = (size_t)gw * CDIM + ((i < 4) ? (lane << 2) + i : 128 + (lane << 2) + i - 4);
        __nv_bfloat16 h = __float2bfloat16_rn(va[i]);
        g_Eh[o] = h;
        g_El[o] = __float2bfloat16_rn(va[i] - __bfloat162float(h));
    }
}

// ---------------- HMMA bf16x3 GEMM + fused top2/enc/kld epilogue ----------
// CTA: 128 rows (blockIdx.y) x 128 codes (blockIdx.x). 8 warps, 2x4, warp 64x32.
// Virtual K=768: chunks 0-3 Xh*Eh, 4-7 Xh*El, 8-11 Xl*Eh; 64-K double-buffered.
#define STR_B   144                 // 72 bf16 padded row (bytes), 16B-aligned rows
#define A_BYTES (128 * STR_B)       // 18432
#define STAGE_B (2 * A_BYTES)       // 36864 (A + B per stage)
#define SMEM_DYN (2 * STAGE_B)      // 73728 (fits 2 CTAs/SM)
__global__ __launch_bounds__(256, 2)
void gemmKernel(const float* __restrict__ G, float* __restrict__ enc) {
    extern __shared__ char dsm[];
    const uint32_t sb = smem_u32(dsm);

    const int tid  = threadIdx.x;
    const int warp = tid >> 5;
    const int lane = tid & 31;
    const int wm   = warp >> 2;          // 0..1
    const int wn   = warp & 3;           // 0..3
    const int m0   = blockIdx.y << 7;
    const int j0   = blockIdx.x << 7;

    float acc[4][4][4];
#pragma unroll
    for (int i = 0; i < 4; i++)
#pragma unroll
        for (int j = 0; j < 4; j++)
#pragma unroll
            for (int k = 0; k < 4; k++) acc[i][j][k] = 0.0f;

    // chunk loader: 4 cp.async of 16B for A, 4 for B
    auto loadChunk = [&](int c, int stage) {
        const __nv_bfloat16* Asrc = (c < 8) ? g_Xh : g_Xl;
        const __nv_bfloat16* Bsrc = (c < 4 || c >= 8) ? g_Eh : g_El;
        const int kb = (c & 3) << 6;
        const uint32_t aBase = sb + (uint32_t)stage * STAGE_B;
        const uint32_t bBase = aBase + A_BYTES;
#pragma unroll
        for (int t = 0; t < 4; t++) {
            int id = tid + (t << 8);
            int r = id >> 3, c16 = id & 7;
            cp16(aBase + r * STR_B + (c16 << 4),
                 Asrc + (size_t)(m0 + r) * CDIM + kb + (c16 << 3));
        }
#pragma unroll
        for (int t = 0; t < 4; t++) {
            int id = tid + (t << 8);
            int r = id >> 3, c16 = id & 7;
            cp16(bBase + r * STR_B + (c16 << 4),
                 Bsrc + (size_t)(j0 + r) * CDIM + kb + (c16 << 3));
        }
        CP_COMMIT();
    };

    loadChunk(0, 0);

#pragma unroll 1
    for (int c = 0; c < 12; c++) {
        if (c + 1 < 12) loadChunk(c + 1, (c + 1) & 1);
        if (c + 1 < 12) { CP_WAIT1(); } else { CP_WAIT0(); }
        __syncthreads();

        const uint32_t aBase = sb + (uint32_t)(c & 1) * STAGE_B;
        const uint32_t bBase = aBase + A_BYTES;
#pragma unroll
        for (int ks = 0; ks < 4; ks++) {
            uint32_t bfr[4][2];
#pragma unroll
            for (int nf = 0; nf < 4; nf++) {
                uint32_t addr = bBase
                    + (uint32_t)((wn << 5) + (nf << 3) + (lane & 7)) * STR_B
                    + (uint32_t)(ks << 5) + (uint32_t)(((lane >> 3) & 1) << 4);
                ldsm2(bfr[nf], addr);
            }
#pragma unroll
            for (int mf = 0; mf < 4; mf++) {
                uint32_t afr[4];
                uint32_t addr = aBase
                    + (uint32_t)((wm << 6) + (mf << 4) + (lane & 15)) * STR_B
                    + (uint32_t)(ks << 5) + (uint32_t)((lane >> 4) << 4);
                ldsm4(afr, addr);
#pragma unroll
                for (int nf = 0; nf < 4; nf++)
                    mma_bf16(acc[mf][nf], afr[0], afr[1], afr[2], afr[3],
                             bfr[nf][0], bfr[nf][1]);
            }
        }
        __syncthreads();
    }

    // -------- epilogue: fragment layout c0=(r,2q) c1=(r,2q+1) c2=(r+8,..) --------
    const int quad = lane >> 2;
    const int q    = lane & 3;
    float kld = 0.0f;
    const float2 z2 = make_float2(0.f, 0.f);

#pragma unroll
    for (int mf = 0; mf < 4; mf++) {
#pragma unroll
        for (int half = 0; half < 2; half++) {
            const int row = m0 + (wm << 6) + (mf << 4) + quad + (half << 3);
            const float xxr = g_xx[row];
            ull   k1 = 0ull;
            float s1 = -3.0e38f, s2 = -3.0e38f;
#pragma unroll
            for (int nf = 0; nf < 4; nf++) {
                const int col = j0 + (wn << 5) + (nf << 3) + (q << 1);
                float c0 = acc[mf][nf][half << 1];
                float c1 = acc[mf][nf][(half << 1) + 1];
                float2 g2 = *(const float2*)(G + (size_t)row * KCODES + col);
                float2 e2 = *(const float2*)(g_ee + col);

                float d0 = (xxr + e2.x) - 2.0f * c0;
                float d1 = (xxr + e2.y) - 2.0f * c1;
                if (d0 < 85.0f) {
                    float pr = 1.0f / (1.0f + expf(d0));
                    kld += pr * logf(fmaxf(pr, 1e-8f));
                }
                if (d1 < 85.0f) {
                    float pr = 1.0f / (1.0f + expf(d1));
                    kld += pr * logf(fmaxf(pr, 1e-8f));
                }
                float s0 = g2.x - d0;
                float s1v = g2.y - d1;
                ull k0 = packKey(s0, col);
                if (k0 > k1) { s2 = s1; k1 = k0; s1 = s0; } else { s2 = fmaxf(s2, s0); }
                ull kk1 = packKey(s1v, col + 1);
                if (kk1 > k1) { s2 = s1; k1 = kk1; s1 = s1v; } else { s2 = fmaxf(s2, s1v); }

                *(float2*)(enc + (size_t)row * KCODES + col) = z2;
            }
            // merge across the 4 quad lanes (xor 1, 2 stay within quad)
#pragma unroll
            for (int x = 1; x <= 2; x <<= 1) {
                ull   ok  = __shfl_xor_sync(0xFFFFFFFFu, k1, x);
                float os1 = __shfl_xor_sync(0xFFFFFFFFu, s1, x);
                float os2 = __shfl_xor_sync(0xFFFFFFFFu, s2, x);
                if (ok > k1) { s2 = fmaxf(fmaxf(s2, os2), s1); k1 = ok; s1 = os1; }
                else         { s2 = fmaxf(fmaxf(s2, os2), os1); }
            }
            if (q == 0) {
                // one slot per (row, 32-col warp segment)
                int slot = (row << 5) + ((int)blockIdx.x << 2) + wn;
                g_pKey[slot] = k1;
                g_pS2[slot]  = s2;
            }
        }
    }

#pragma unroll
    for (int off = 16; off; off >>= 1) kld += __shfl_down_sync(0xFFFFFFFFu, kld, off);
    if (lane == 0 && kld != 0.0f) atomicAdd(&g_kldSum, kld);
}

// ---------------- merge partials -> idx or rescue flag ----------------
__global__ void mergeKernel() {
    int row = blockIdx.x * blockDim.x + threadIdx.x;
    if (row >= N_ROWS) return;
    ull best = 0ull;
#pragma unroll
    for (int t = 0; t < 32; t++) best = max(best, g_pKey[(row << 5) + t]);
    float runner = -3.0e38f;
#pragma unroll
    for (int t = 0; t < 32; t++) {
        ull k = g_pKey[(row << 5) + t];
        if (k != best) runner = fmaxf(runner, decodeKey(k));
        runner = fmaxf(runner, g_pS2[(row << 5) + t]);
    }
    float margin = decodeKey(best) - runner;
    if (margin < DELTA) {
        int p = atomicAdd(&g_nRescue, 1);
        g_rescueRows[p] = row;
    } else {
        g_rowIdx[row] = 1023 - (int)(unsigned)(best & 0xFFFFFFFFull);
    }
}

// ---------------- fp32 rescue for tight rows ----------------
__global__ __launch_bounds__(256)
void rescueKernel(const float* __restrict__ E, const float* __restrict__ G) {
    __shared__ float sx[CDIM];
    __shared__ ull   rk[8];
    const int tid = threadIdx.x;
    const int nR  = g_nRescue;
    for (int i = blockIdx.x; i < nR; i += gridDim.x) {
        int row = g_rescueRows[i];
        sx[tid] = g_Xt[(size_t)row * CDIM + tid];
        __syncthreads();
        float xxr = g_xx[row];
        ull key = 0ull;
#pragma unroll 1
        for (int cc = 0; cc < 4; cc++) {
            int code = tid + (cc << 8);
            const float* e = E + (size_t)code * CDIM;
            float acc = 0.0f;
#pragma unroll 8
            for (int k = 0; k < CDIM; k++) acc = fmaf(sx[k], e[k], acc);
            float d = (xxr + g_ee[code]) - 2.0f * acc;
            float s = G[(size_t)row * KCODES + code] - d;
            ull kk = packKey(s, code);
            key = max(key, kk);
        }
#pragma unroll
        for (int off = 16; off; off >>= 1)
            key = max(key, __shfl_down_sync(0xFFFFFFFFu, key, off));
        if ((tid & 31) == 0) rk[tid >> 5] = key;
        __syncthreads();
        if (tid == 0) {
            ull b = rk[0];
#pragma unroll
            for (int w = 1; w < 8; w++) b = max(b, rk[w]);
            g_rowIdx[row] = 1023 - (int)(unsigned)(b & 0xFFFFFFFFull);
        }
        __syncthreads();
    }
}

// ---------------- finish: one-hot scatter, quantized NCHW, e_latent, hist ----
__global__ __launch_bounds__(256)
void finishKernel(const float* __restrict__ E, float* __restrict__ out) {
    __shared__ int   sIdx[32];
    __shared__ float sQ[32 * 257];
    __shared__ float r2[8];

    const int n0  = blockIdx.x << 5;
    const int tid = threadIdx.x;

    if (tid < 32) {
        int idx = g_rowIdx[n0 + tid];
        sIdx[tid] = idx;
        out[ENC_OFF + (size_t)(n0 + tid) * KCODES + idx] = 1.0f;
        atomicAdd(&g_counts[idx], 1u);
    }
    __syncthreads();

    float accum = 0.0f;
    const int c = tid;
#pragma unroll 4
    for (int i = 0; i < 32; i++) {
        float v = E[(size_t)sIdx[i] * CDIM + c];
        float x = g_Xt[(size_t)(n0 + i) * CDIM + c];
        float dlt = v - x;
        accum += dlt * dlt;
        sQ[i * 257 + c] = v;
    }
    __syncthreads();

    const int b   = n0 >> 10;
    const int hw0 = n0 & 1023;
    float* qb = out + QUANT_OFF + (size_t)b * CDIM * HWDIM;
#pragma unroll 4
    for (int it = 0; it < 32; it++) {
        int f  = it * 256 + tid;
        int cc = f >> 5;
        int ii = f & 31;
        qb[(size_t)cc * HWDIM + hw0 + ii] = sQ[ii * 257 + cc];
    }

#pragma unroll
    for (int off = 16; off; off >>= 1) accum += __shfl_down_sync(0xFFFFFFFFu, accum, off);
    if ((tid & 31) == 0) r2[tid >> 5] = accum;
    __syncthreads();
    if (tid == 0) {
        float s = 0.0f;
#pragma unroll
        for (int w = 0; w < 8; w++) s += r2[w];
        atomicAdd(&g_elatSum, s);
    }
}

// ---------------- scalars ----------------
__global__ void lossKernel(float* __restrict__ out) {
    __shared__ float red[32];
    int t = threadIdx.x;
    float avg  = (float)g_counts[t] * (1.0f / 32768.0f);
    float term = avg * logf(avg + 1e-10f);
#pragma unroll
    for (int off = 16; off; off >>= 1) term += __shfl_down_sync(0xFFFFFFFFu, term, off);
    if ((t & 31) == 0) red[t >> 5] = term;
    __syncthreads();
    if (t < 32) {
        float v = red[t];
#pragma unroll
        for (int off = 16; off; off >>= 1) v += __shfl_down_sync(0xFFFFFFFFu, v, off);
        if (t == 0) {
            float perp = expf(-v);
            float eLat = g_elatSum * (1.0f / 8388608.0f);
            float kld  = g_kldSum * (1.0f / 32768.0f);
            float loss = 1.5f * (kld + eLat * (kld / fmaxf(eLat, 1e-8f)));
            out[0]        = loss;
            out[PERP_OFF] = perp;
        }
    }
}

// ---------------- launch ----------------
extern "C" void kernel_launch(void* const* d_in, const int* in_sizes, int n_in,
                              void* d_out, int out_size) {
    const float* inp = (const float*)d_in[0];
    const float* emb = (const float*)d_in[1];
    const float* gum = (const float*)d_in[2];
    float* out = (float*)d_out;
    float* enc = out + ENC_OFF;

    cudaFuncSetAttribute(gemmKernel, cudaFuncAttributeMaxDynamicSharedMemorySize, SMEM_DYN);

    initKernel<<<128, 256>>>();
    transConvKernel<<<dim3(32, 8, 32), dim3(32, 8)>>>(inp);
    sumsqEConv<<<128, 256>>>(emb);
    gemmKernel<<<dim3(KCODES / 128, N_ROWS / 128), 256, SMEM_DYN>>>(gum, enc);
    mergeKernel<<<128, 256>>>();
    rescueKernel<<<256, 256>>>(emb, gum);
    finishKernel<<<N_ROWS / 32, 256>>>(emb, out);
    lossKernel<<<1, 1024>>>(out);
}

// round 8
// speedup vs baseline: 1.3869x; 1.0290x over previous
#include <cuda_runtime.h>
#include <cuda_bf16.h>
#include <cstdint>

typedef unsigned long long ull;

#define CDIM    256
#define HWDIM   1024
#define N_ROWS  32768
#define KCODES  1024

#define QUANT_OFF 1
#define PERP_OFF  8388609
#define ENC_OFF   8388610

#define DELTA   0.012f

// ---------------- scratch ----------------
__device__ __nv_bfloat16  g_Xh[N_ROWS * CDIM];
__device__ __nv_bfloat16  g_Xl[N_ROWS * CDIM];
__device__ __nv_bfloat16  g_Eh[KCODES * CDIM];
__device__ __nv_bfloat16  g_El[KCODES * CDIM];
__device__ float          g_xx[N_ROWS];
__device__ float          g_ee[KCODES];
__device__ ull            g_pKey[N_ROWS * 32];  // per (row, 32-col segment) top1
__device__ float          g_pS2[N_ROWS * 32];   // per-segment runner-up score
__device__ int            g_rowIdx[N_ROWS];
__device__ int            g_rescueRows[N_ROWS];
__device__ int            g_nRescue;
__device__ unsigned int   g_counts[KCODES];
__device__ float          g_kldSum;

// ---------------- helpers ----------------
__device__ __forceinline__ uint32_t smem_u32(const void* p) {
    uint32_t a;
    asm("{ .reg .u64 t; cvta.to.shared.u64 t, %1; cvt.u32.u64 %0, t; }" : "=r"(a) : "l"(p));
    return a;
}
__device__ __forceinline__ void cp16(uint32_t dst, const void* src) {
    asm volatile("cp.async.cg.shared.global [%0], [%1], 16;" :: "r"(dst), "l"(src));
}
#define CP_COMMIT() asm volatile("cp.async.commit_group;" ::: "memory")
#define CP_WAIT1()  asm volatile("cp.async.wait_group 1;" ::: "memory")
#define CP_WAIT0()  asm volatile("cp.async.wait_group 0;" ::: "memory")

__device__ __forceinline__ void ldsm4(uint32_t* r, uint32_t a) {
    asm volatile("ldmatrix.sync.aligned.m8n8.x4.shared.b16 {%0,%1,%2,%3}, [%4];"
                 : "=r"(r[0]), "=r"(r[1]), "=r"(r[2]), "=r"(r[3]) : "r"(a));
}
__device__ __forceinline__ void mma_bf16(float* c, uint32_t a0, uint32_t a1,
                                         uint32_t a2, uint32_t a3,
                                         uint32_t b0, uint32_t b1) {
    asm volatile("mma.sync.aligned.m16n8k16.row.col.f32.bf16.bf16.f32 "
                 "{%0,%1,%2,%3}, {%4,%5,%6,%7}, {%8,%9}, {%0,%1,%2,%3};"
                 : "+f"(c[0]), "+f"(c[1]), "+f"(c[2]), "+f"(c[3])
                 : "r"(a0), "r"(a1), "r"(a2), "r"(a3), "r"(b0), "r"(b1));
}

__device__ __forceinline__ ull packKey(float s, int idx) {
    unsigned u = __float_as_uint(s);
    u = (u & 0x80000000u) ? ~u : (u | 0x80000000u);
    return ((ull)u << 32) | (unsigned)(1023 - idx);
}
__device__ __forceinline__ float decodeKey(ull k) {
    unsigned u = (unsigned)(k >> 32);
    unsigned v = (u & 0x80000000u) ? (u & 0x7FFFFFFFu) : ~u;
    return __uint_as_float(v);
}

// ---------------- init ----------------
__global__ void initKernel() {
    int t = blockIdx.x * blockDim.x + threadIdx.x;
    if (t < N_ROWS) g_xx[t] = 0.0f;
    if (t < KCODES) g_counts[t] = 0u;
    if (t == 0) { g_kldSum = 0.0f; g_nRescue = 0; }
}

// ------- NCHW -> [N,C] bf16 hi/lo split + fused ||x||^2 (no fp32 Xt) ---------
__global__ void transConvKernel(const float* __restrict__ in) {
    __shared__ float tile[32][33];
    int b   = blockIdx.z;
    int hw0 = blockIdx.x << 5;
    int c0  = blockIdx.y << 5;
    const float* p = in + (size_t)b * CDIM * HWDIM;
#pragma unroll
    for (int j = 0; j < 4; j++) {
        int cl = threadIdx.y + (j << 3);
        tile[cl][threadIdx.x] = p[(size_t)(c0 + cl) * HWDIM + hw0 + threadIdx.x];
    }
    __syncthreads();
#pragma unroll
    for (int j = 0; j < 4; j++) {
        int hwl = threadIdx.y + (j << 3);
        int row = b * HWDIM + hw0 + hwl;
        size_t o = (size_t)row * CDIM + c0 + threadIdx.x;
        float v = tile[threadIdx.x][hwl];
        __nv_bfloat16 h = __float2bfloat16_rn(v);
        g_Xh[o] = h;
        g_Xl[o] = __float2bfloat16_rn(v - __bfloat162float(h));
        float s = v * v;
#pragma unroll
        for (int off = 16; off; off >>= 1) s += __shfl_xor_sync(0xFFFFFFFFu, s, off);
        if (threadIdx.x == 0) atomicAdd(&g_xx[row], s);
    }
}

// ---------------- E: sum-of-squares + bf16 hi/lo split (fused) ----------------
__global__ void sumsqEConv(const float* __restrict__ E) {
    int gw   = (blockIdx.x * blockDim.x + threadIdx.x) >> 5;
    int lane = threadIdx.x & 31;
    if (gw >= KCODES) return;
    const float* p = E + (size_t)gw * CDIM;
    float4 a = *(const float4*)(p + (lane << 2));
    float4 b = *(const float4*)(p + 128 + (lane << 2));
    float s = a.x*a.x + a.y*a.y + a.z*a.z + a.w*a.w
            + b.x*b.x + b.y*b.y + b.z*b.z + b.w*b.w;
#pragma unroll
    for (int off = 16; off; off >>= 1) s += __shfl_xor_sync(0xFFFFFFFFu, s, off);
    if (lane == 0) g_ee[gw] = s;

    float va[8] = { a.x, a.y, a.z, a.w, b.x, b.y, b.z, b.w };
#pragma unroll
    for (int i = 0; i < 8; i++) {
        size_t o = (size_t)gw * CDIM + ((i < 4) ? (lane << 2) + i : 128 + (lane << 2) + i - 4);
        __nv_bfloat16 h = __float2bfloat16_rn(va[i]);
        g_Eh[o] = h;
        g_El[o] = __float2bfloat16_rn(va[i] - __bfloat162float(h));
    }
}

// ---------------- HMMA bf16x3 GEMM + fused top2/enc/kld epilogue ----------
// CTA: 128 rows x 128 codes, 8 warps (2x4), warp 64x32. Virtual K=768:
// chunks 0-3 Xh*Eh, 4-7 Xh*El, 8-11 Xl*Eh. 3-stage cp.async ring, 1 sync/chunk.
#define STR_B   144                 // 72 bf16 padded row (bytes), 16B-aligned
#define A_BYTES (128 * STR_B)       // 18432
#define STAGE_B (2 * A_BYTES)       // 36864 (A + B per stage)
#define SMEM_DYN (3 * STAGE_B)      // 110592 (3 stages; 2 CTAs/SM = 216KB)
__global__ __launch_bounds__(256, 2)
void gemmKernel(const float* __restrict__ G, float* __restrict__ enc) {
    extern __shared__ char dsm[];
    const uint32_t sb = smem_u32(dsm);

    const int tid  = threadIdx.x;
    const int warp = tid >> 5;
    const int lane = tid & 31;
    const int wm   = warp >> 2;          // 0..1
    const int wn   = warp & 3;           // 0..3
    const int m0   = blockIdx.y << 7;
    const int j0   = blockIdx.x << 7;

    float acc[4][4][4];
#pragma unroll
    for (int i = 0; i < 4; i++)
#pragma unroll
        for (int j = 0; j < 4; j++)
#pragma unroll
            for (int k = 0; k < 4; k++) acc[i][j][k] = 0.0f;

    auto loadChunk = [&](int c, int stage) {
        const __nv_bfloat16* Asrc = (c < 8) ? g_Xh : g_Xl;
        const __nv_bfloat16* Bsrc = (c < 4 || c >= 8) ? g_Eh : g_El;
        const int kb = (c & 3) << 6;
        const uint32_t aBase = sb + (uint32_t)stage * STAGE_B;
        const uint32_t bBase = aBase + A_BYTES;
#pragma unroll
        for (int t = 0; t < 4; t++) {
            int id = tid + (t << 8);
            int r = id >> 3, c16 = id & 7;
            cp16(aBase + r * STR_B + (c16 << 4),
                 Asrc + (size_t)(m0 + r) * CDIM + kb + (c16 << 3));
        }
#pragma unroll
        for (int t = 0; t < 4; t++) {
            int id = tid + (t << 8);
            int r = id >> 3, c16 = id & 7;
            cp16(bBase + r * STR_B + (c16 << 4),
                 Bsrc + (size_t)(j0 + r) * CDIM + kb + (c16 << 3));
        }
        CP_COMMIT();
    };

    loadChunk(0, 0);
    loadChunk(1, 1);

#pragma unroll 1
    for (int c = 0; c < 12; c++) {
        // after wait+sync: all threads' group-c data visible, compute(c-1) done
        if (c < 11) { CP_WAIT1(); } else { CP_WAIT0(); }
        __syncthreads();
        if (c + 2 < 12) loadChunk(c + 2, (c + 2) % 3);

        const uint32_t aBase = sb + (uint32_t)(c % 3) * STAGE_B;
        const uint32_t bBase = aBase + A_BYTES;
#pragma unroll
        for (int ks = 0; ks < 4; ks++) {
            // B: two ldsm.x4, each covering an nf pair (both k halves)
            uint32_t bfr[4][2];
#pragma unroll
            for (int nfp = 0; nfp < 2; nfp++) {
                int g = lane >> 3;                    // 0..3
                int rowb = (wn << 5) + (nfp << 4) + ((g >> 1) << 3) + (lane & 7);
                uint32_t addr = bBase + (uint32_t)rowb * STR_B
                              + (uint32_t)(ks << 5) + (uint32_t)((g & 1) << 4);
                uint32_t r4[4];
                ldsm4(r4, addr);
                bfr[(nfp << 1) + 0][0] = r4[0];
                bfr[(nfp << 1) + 0][1] = r4[1];
                bfr[(nfp << 1) + 1][0] = r4[2];
                bfr[(nfp << 1) + 1][1] = r4[3];
            }
#pragma unroll
            for (int mf = 0; mf < 4; mf++) {
                uint32_t afr[4];
                uint32_t addr = aBase
                    + (uint32_t)((wm << 6) + (mf << 4) + (lane & 15)) * STR_B
                    + (uint32_t)(ks << 5) + (uint32_t)((lane >> 4) << 4);
                ldsm4(afr, addr);
#pragma unroll
                for (int nf = 0; nf < 4; nf++)
                    mma_bf16(acc[mf][nf], afr[0], afr[1], afr[2], afr[3],
                             bfr[nf][0], bfr[nf][1]);
            }
        }
    }
    __syncthreads();

    // -------- epilogue: fragment c0=(r,2q) c1=(r,2q+1) c2/c3=(r+8,..) --------
    const int quad = lane >> 2;
    const int q    = lane & 3;
    float kld = 0.0f;
    const float2 z2 = make_float2(0.f, 0.f);

#pragma unroll
    for (int mf = 0; mf < 4; mf++) {
#pragma unroll
        for (int half = 0; half < 2; half++) {
            const int row = m0 + (wm << 6) + (mf << 4) + quad + (half << 3);
            const float xxr = g_xx[row];
            ull   k1 = 0ull;
            float s1 = -3.0e38f, s2 = -3.0e38f;
#pragma unroll
            for (int nf = 0; nf < 4; nf++) {
                const int col = j0 + (wn << 5) + (nf << 3) + (q << 1);
                float c0 = acc[mf][nf][half << 1];
                float c1 = acc[mf][nf][(half << 1) + 1];
                float2 g2 = *(const float2*)(G + (size_t)row * KCODES + col);
                float2 e2 = *(const float2*)(g_ee + col);

                float d0 = (xxr + e2.x) - 2.0f * c0;
                float d1 = (xxr + e2.y) - 2.0f * c1;
                if (d0 < 85.0f) {
                    float pr = 1.0f / (1.0f + expf(d0));
                    kld += pr * logf(fmaxf(pr, 1e-8f));
                }
                if (d1 < 85.0f) {
                    float pr = 1.0f / (1.0f + expf(d1));
                    kld += pr * logf(fmaxf(pr, 1e-8f));
                }
                float s0 = g2.x - d0;
                float s1v = g2.y - d1;
                ull k0 = packKey(s0, col);
                if (k0 > k1) { s2 = s1; k1 = k0; s1 = s0; } else { s2 = fmaxf(s2, s0); }
                ull kk1 = packKey(s1v, col + 1);
                if (kk1 > k1) { s2 = s1; k1 = kk1; s1 = s1v; } else { s2 = fmaxf(s2, s1v); }

                *(float2*)(enc + (size_t)row * KCODES + col) = z2;
            }
#pragma unroll
            for (int x = 1; x <= 2; x <<= 1) {
                ull   ok  = __shfl_xor_sync(0xFFFFFFFFu, k1, x);
                float os1 = __shfl_xor_sync(0xFFFFFFFFu, s1, x);
                float os2 = __shfl_xor_sync(0xFFFFFFFFu, s2, x);
                if (ok > k1) { s2 = fmaxf(fmaxf(s2, os2), s1); k1 = ok; s1 = os1; }
                else         { s2 = fmaxf(fmaxf(s2, os2), os1); }
            }
            if (q == 0) {
                int slot = (row << 5) + ((int)blockIdx.x << 2) + wn;
                g_pKey[slot] = k1;
                g_pS2[slot]  = s2;
            }
        }
    }

#pragma unroll
    for (int off = 16; off; off >>= 1) kld += __shfl_down_sync(0xFFFFFFFFu, kld, off);
    if (lane == 0 && kld != 0.0f) atomicAdd(&g_kldSum, kld);
}

// ---------------- merge partials -> idx or rescue flag ----------------
__global__ void mergeKernel() {
    int row = blockIdx.x * blockDim.x + threadIdx.x;
    if (row >= N_ROWS) return;
    ull best = 0ull;
#pragma unroll
    for (int t = 0; t < 32; t++) best = max(best, g_pKey[(row << 5) + t]);
    float runner = -3.0e38f;
#pragma unroll
    for (int t = 0; t < 32; t++) {
        ull k = g_pKey[(row << 5) + t];
        if (k != best) runner = fmaxf(runner, decodeKey(k));
        runner = fmaxf(runner, g_pS2[(row << 5) + t]);
    }
    float margin = decodeKey(best) - runner;
    if (margin < DELTA) {
        int p = atomicAdd(&g_nRescue, 1);
        g_rescueRows[p] = row;
    } else {
        g_rowIdx[row] = 1023 - (int)(unsigned)(best & 0xFFFFFFFFull);
    }
}

// ------- fp32 rescue for tight rows (exact x read from NCHW input) ----------
__global__ __launch_bounds__(256)
void rescueKernel(const float* __restrict__ in, const float* __restrict__ E,
                  const float* __restrict__ G) {
    __shared__ float sx[CDIM];
    __shared__ ull   rk[8];
    const int tid = threadIdx.x;
    const int nR  = g_nRescue;
    for (int i = blockIdx.x; i < nR; i += gridDim.x) {
        int row = g_rescueRows[i];
        int b   = row >> 10;
        int hw  = row & 1023;
        sx[tid] = in[(size_t)b * CDIM * HWDIM + (size_t)tid * HWDIM + hw];
        __syncthreads();
        float xxr = g_xx[row];
        ull key = 0ull;
#pragma unroll 1
        for (int cc = 0; cc < 4; cc++) {
            int code = tid + (cc << 8);
            const float* e = E + (size_t)code * CDIM;
            float acc = 0.0f;
#pragma unroll 8
            for (int k = 0; k < CDIM; k++) acc = fmaf(sx[k], e[k], acc);
            float d = (xxr + g_ee[code]) - 2.0f * acc;
            float s = G[(size_t)row * KCODES + code] - d;
            ull kk = packKey(s, code);
            key = max(key, kk);
        }
#pragma unroll
        for (int off = 16; off; off >>= 1)
            key = max(key, __shfl_down_sync(0xFFFFFFFFu, key, off));
        if ((tid & 31) == 0) rk[tid >> 5] = key;
        __syncthreads();
        if (tid == 0) {
            ull b2 = rk[0];
#pragma unroll
            for (int w = 1; w < 8; w++) b2 = max(b2, rk[w]);
            g_rowIdx[row] = 1023 - (int)(unsigned)(b2 & 0xFFFFFFFFull);
        }
        __syncthreads();
    }
}

// ---------------- finish: one-hot scatter, quantized NCHW, histogram ----------
__global__ __launch_bounds__(256)
void finishKernel(const float* __restrict__ E, float* __restrict__ out) {
    __shared__ int   sIdx[32];
    __shared__ float sQ[32 * 257];

    const int n0  = blockIdx.x << 5;
    const int tid = threadIdx.x;

    if (tid < 32) {
        int idx = g_rowIdx[n0 + tid];
        sIdx[tid] = idx;
        out[ENC_OFF + (size_t)(n0 + tid) * KCODES + idx] = 1.0f;
        atomicAdd(&g_counts[idx], 1u);
    }
    __syncthreads();

    const int c = tid;
#pragma unroll 4
    for (int i = 0; i < 32; i++)
        sQ[i * 257 + c] = E[(size_t)sIdx[i] * CDIM + c];
    __syncthreads();

    const int b   = n0 >> 10;
    const int hw0 = n0 & 1023;
    float* qb = out + QUANT_OFF + (size_t)b * CDIM * HWDIM;
#pragma unroll 4
    for (int it = 0; it < 32; it++) {
        int f  = it * 256 + tid;
        int cc = f >> 5;
        int ii = f & 31;
        qb[(size_t)cc * HWDIM + hw0 + ii] = sQ[ii * 257 + cc];
    }
}

// ---------------- scalars ----------------
// loss = C*(kld + e_lat*stopgrad(kld/clip(e_lat,1e-8))). e_lat >> 1e-8 always,
// so the ratio is exactly 1 and loss = 1.5*2*kld, independent of e_lat.
__global__ void lossKernel(float* __restrict__ out) {
    __shared__ float red[32];
    int t = threadIdx.x;
    float avg  = (float)g_counts[t] * (1.0f / 32768.0f);
    float term = avg * logf(avg + 1e-10f);
#pragma unroll
    for (int off = 16; off; off >>= 1) term += __shfl_down_sync(0xFFFFFFFFu, term, off);
    if ((t & 31) == 0) red[t >> 5] = term;
    __syncthreads();
    if (t < 32) {
        float v = red[t];
#pragma unroll
        for (int off = 16; off; off >>= 1) v += __shfl_down_sync(0xFFFFFFFFu, v, off);
        if (t == 0) {
            float kld = g_kldSum * (1.0f / 32768.0f);
            out[0]        = 3.0f * kld;
            out[PERP_OFF] = expf(-v);
        }
    }
}

// ---------------- launch ----------------
extern "C" void kernel_launch(void* const* d_in, const int* in_sizes, int n_in,
                              void* d_out, int out_size) {
    const float* inp = (const float*)d_in[0];
    const float* emb = (const float*)d_in[1];
    const float* gum = (const float*)d_in[2];
    float* out = (float*)d_out;
    float* enc = out + ENC_OFF;

    cudaFuncSetAttribute(gemmKernel, cudaFuncAttributeMaxDynamicSharedMemorySize, SMEM_DYN);

    initKernel<<<128, 256>>>();
    transConvKernel<<<dim3(32, 8, 32), dim3(32, 8)>>>(inp);
    sumsqEConv<<<128, 256>>>(emb);
    gemmKernel<<<dim3(KCODES / 128, N_ROWS / 128), 256, SMEM_DYN>>>(gum, enc);
    mergeKernel<<<128, 256>>>();
    rescueKernel<<<256, 256>>>(inp, emb, gum);
    finishKernel<<<N_ROWS / 32, 256>>>(emb, out);
    lossKernel<<<1, 1024>>>(out);
}

// round 9
// speedup vs baseline: 1.4726x; 1.0618x over previous
#include <cuda_runtime.h>
#include <cuda_fp16.h>
#include <cstdint>

typedef unsigned long long ull;

#define CDIM    256
#define HWDIM   1024
#define N_ROWS  32768
#define KCODES  1024

#define QUANT_OFF 1
#define PERP_OFF  8388609
#define ENC_OFF   8388610

#define DELTA   0.03f

// ---------------- scratch ----------------
__device__ __half         g_Xh[N_ROWS * CDIM];
__device__ __half         g_Eh[KCODES * CDIM];
__device__ __half         g_El[KCODES * CDIM];
__device__ float          g_xx[N_ROWS];
__device__ float          g_ee[KCODES];
__device__ ull            g_pKey[N_ROWS * 32];  // per (row, 32-col segment) top1
__device__ float          g_pS2[N_ROWS * 32];   // per-segment runner-up score
__device__ int            g_rowIdx[N_ROWS];
__device__ int            g_rescueRows[N_ROWS];
__device__ int            g_nRescue;
__device__ unsigned int   g_counts[KCODES];
__device__ float          g_kldSum;

// ---------------- helpers ----------------
__device__ __forceinline__ uint32_t smem_u32(const void* p) {
    uint32_t a;
    asm("{ .reg .u64 t; cvta.to.shared.u64 t, %1; cvt.u32.u64 %0, t; }" : "=r"(a) : "l"(p));
    return a;
}
__device__ __forceinline__ void cp16(uint32_t dst, const void* src) {
    asm volatile("cp.async.cg.shared.global [%0], [%1], 16;" :: "r"(dst), "l"(src));
}
#define CP_COMMIT() asm volatile("cp.async.commit_group;" ::: "memory")
#define CP_WAIT1()  asm volatile("cp.async.wait_group 1;" ::: "memory")
#define CP_WAIT0()  asm volatile("cp.async.wait_group 0;" ::: "memory")

__device__ __forceinline__ void ldsm4(uint32_t* r, uint32_t a) {
    asm volatile("ldmatrix.sync.aligned.m8n8.x4.shared.b16 {%0,%1,%2,%3}, [%4];"
                 : "=r"(r[0]), "=r"(r[1]), "=r"(r[2]), "=r"(r[3]) : "r"(a));
}
__device__ __forceinline__ void mma_f16(float* c, uint32_t a0, uint32_t a1,
                                        uint32_t a2, uint32_t a3,
                                        uint32_t b0, uint32_t b1) {
    asm volatile("mma.sync.aligned.m16n8k16.row.col.f32.f16.f16.f32 "
                 "{%0,%1,%2,%3}, {%4,%5,%6,%7}, {%8,%9}, {%0,%1,%2,%3};"
                 : "+f"(c[0]), "+f"(c[1]), "+f"(c[2]), "+f"(c[3])
                 : "r"(a0), "r"(a1), "r"(a2), "r"(a3), "r"(b0), "r"(b1));
}

__device__ __forceinline__ ull packKey(float s, int idx) {
    unsigned u = __float_as_uint(s);
    u = (u & 0x80000000u) ? ~u : (u | 0x80000000u);
    return ((ull)u << 32) | (unsigned)(1023 - idx);
}
__device__ __forceinline__ float decodeKey(ull k) {
    unsigned u = (unsigned)(k >> 32);
    unsigned v = (u & 0x80000000u) ? (u & 0x7FFFFFFFu) : ~u;
    return __uint_as_float(v);
}

// ---------------- init ----------------
__global__ void initKernel() {
    int t = blockIdx.x * blockDim.x + threadIdx.x;
    if (t < N_ROWS) g_xx[t] = 0.0f;
    if (t < KCODES) g_counts[t] = 0u;
    if (t == 0) { g_kldSum = 0.0f; g_nRescue = 0; }
}

// ------- NCHW -> [N,C] fp16 + fused ||x||^2 ----------
__global__ void transConvKernel(const float* __restrict__ in) {
    __shared__ float tile[32][33];
    int b   = blockIdx.z;
    int hw0 = blockIdx.x << 5;
    int c0  = blockIdx.y << 5;
    const float* p = in + (size_t)b * CDIM * HWDIM;
#pragma unroll
    for (int j = 0; j < 4; j++) {
        int cl = threadIdx.y + (j << 3);
        tile[cl][threadIdx.x] = p[(size_t)(c0 + cl) * HWDIM + hw0 + threadIdx.x];
    }
    __syncthreads();
#pragma unroll
    for (int j = 0; j < 4; j++) {
        int hwl = threadIdx.y + (j << 3);
        int row = b * HWDIM + hw0 + hwl;
        size_t o = (size_t)row * CDIM + c0 + threadIdx.x;
        float v = tile[threadIdx.x][hwl];
        g_Xh[o] = __float2half_rn(v);
        float s = v * v;
#pragma unroll
        for (int off = 16; off; off >>= 1) s += __shfl_xor_sync(0xFFFFFFFFu, s, off);
        if (threadIdx.x == 0) atomicAdd(&g_xx[row], s);
    }
}

// ---------------- E: sum-of-squares + fp16 hi/lo split ----------------
__global__ void sumsqEConv(const float* __restrict__ E) {
    int gw   = (blockIdx.x * blockDim.x + threadIdx.x) >> 5;
    int lane = threadIdx.x & 31;
    if (gw >= KCODES) return;
    const float* p = E + (size_t)gw * CDIM;
    float4 a = *(const float4*)(p + (lane << 2));
    float4 b = *(const float4*)(p + 128 + (lane << 2));
    float s = a.x*a.x + a.y*a.y + a.z*a.z + a.w*a.w
            + b.x*b.x + b.y*b.y + b.z*b.z + b.w*b.w;
#pragma unroll
    for (int off = 16; off; off >>= 1) s += __shfl_xor_sync(0xFFFFFFFFu, s, off);
    if (lane == 0) g_ee[gw] = s;

    float va[8] = { a.x, a.y, a.z, a.w, b.x, b.y, b.z, b.w };
#pragma unroll
    for (int i = 0; i < 8; i++) {
        size_t o = (size_t)gw * CDIM + ((i < 4) ? (lane << 2) + i : 128 + (lane << 2) + i - 4);
        __half h = __float2half_rn(va[i]);
        g_Eh[o] = h;
        g_El[o] = __float2half_rn(va[i] - __half2float(h));
    }
}

// ---------------- HMMA fp16 2-term GEMM + fused top2/enc/kld epilogue -------
// CTA: 128 rows x 128 codes, 8 warps (2x4), warp 64x32. Virtual K=512:
// chunk c: kb=c>>1, B = (c&1)? El : Eh; A = Xh always (resident in smem).
// A: 128x256 fp16, 512B rows, XOR-swizzled 16B segments (low 3 bits ^ row&7).
// B: 3-stage ring, 128x64 fp16 tiles, 128B rows, XOR-swizzled.
#define A_BYTES  65536
#define B_BYTES  16384
#define SMEM_DYN (A_BYTES + 3 * B_BYTES)   // 114688; 2 CTAs/SM = 229376 <= 228KB
__global__ __launch_bounds__(256, 2)
void gemmKernel(const float* __restrict__ G, float* __restrict__ enc) {
    extern __shared__ char dsm[];
    const uint32_t sb = smem_u32(dsm);

    const int tid  = threadIdx.x;
    const int warp = tid >> 5;
    const int lane = tid & 31;
    const int wm   = warp >> 2;          // 0..1
    const int wn   = warp & 3;           // 0..3
    const int m0   = blockIdx.y << 7;
    const int j0   = blockIdx.x << 7;

    float acc[4][4][4];
#pragma unroll
    for (int i = 0; i < 4; i++)
#pragma unroll
        for (int j = 0; j < 4; j++)
#pragma unroll
            for (int k = 0; k < 4; k++) acc[i][j][k] = 0.0f;

    // ---- A: load all 128x256 fp16, swizzled, one cp.async group ----
#pragma unroll
    for (int t = 0; t < 16; t++) {
        int id = tid + (t << 8);
        int r = id >> 5, k16 = id & 31;
        uint32_t sw = (uint32_t)((k16 & 24) | ((k16 ^ r) & 7));
        cp16(sb + (uint32_t)r * 512u + (sw << 4),
             g_Xh + (size_t)(m0 + r) * CDIM + (k16 << 3));
    }
    CP_COMMIT();

    auto loadB = [&](int c) {
        const __half* Bsrc = (c & 1) ? g_El : g_Eh;
        const int kb = (c >> 1) << 6;
        const uint32_t bBase = sb + A_BYTES + (uint32_t)(c % 3) * B_BYTES;
#pragma unroll
        for (int t = 0; t < 4; t++) {
            int id = tid + (t << 8);
            int r = id >> 3, k16 = id & 7;
            cp16(bBase + (uint32_t)r * 128u + (uint32_t)((k16 ^ (r & 7)) << 4),
                 Bsrc + (size_t)(j0 + r) * CDIM + kb + (k16 << 3));
        }
        CP_COMMIT();
    };

    loadB(0);
    loadB(1);

#pragma unroll 1
    for (int c = 0; c < 8; c++) {
        if (c < 7) { CP_WAIT1(); } else { CP_WAIT0(); }
        __syncthreads();
        if (c + 2 < 8) loadB(c + 2);

        const int kb = c >> 1;
        const uint32_t bBase = sb + A_BYTES + (uint32_t)(c % 3) * B_BYTES;
#pragma unroll
        for (int ks = 0; ks < 4; ks++) {
            // B: two ldsm.x4, each covering an nf pair (both k halves)
            uint32_t bfr[4][2];
#pragma unroll
            for (int nfp = 0; nfp < 2; nfp++) {
                int g = lane >> 3;                    // 0..3
                int rowb = (wn << 5) + (nfp << 4) + ((g >> 1) << 3) + (lane & 7);
                int k16 = (ks << 1) + (g & 1);
                uint32_t addr = bBase + (uint32_t)rowb * 128u
                              + (uint32_t)((k16 ^ (rowb & 7)) << 4);
                uint32_t r4[4];
                ldsm4(r4, addr);
                bfr[(nfp << 1) + 0][0] = r4[0];
                bfr[(nfp << 1) + 0][1] = r4[1];
                bfr[(nfp << 1) + 1][0] = r4[2];
                bfr[(nfp << 1) + 1][1] = r4[3];
            }
#pragma unroll
            for (int mf = 0; mf < 4; mf++) {
                int rowa = (wm << 6) + (mf << 4) + (lane & 15);
                int k16  = (kb << 3) + (ks << 1) + (lane >> 4);
                uint32_t sw = (uint32_t)((k16 & 24) | ((k16 ^ rowa) & 7));
                uint32_t afr[4];
                ldsm4(afr, sb + (uint32_t)rowa * 512u + (sw << 4));
#pragma unroll
                for (int nf = 0; nf < 4; nf++)
                    mma_f16(acc[mf][nf], afr[0], afr[1], afr[2], afr[3],
                            bfr[nf][0], bfr[nf][1]);
            }
        }
    }
    __syncthreads();

    // -------- epilogue: fragment c0=(r,2q) c1=(r,2q+1) c2/c3=(r+8,..) --------
    const int quad = lane >> 2;
    const int q    = lane & 3;
    float kld = 0.0f;
    const float2 z2 = make_float2(0.f, 0.f);

#pragma unroll
    for (int mf = 0; mf < 4; mf++) {
#pragma unroll
        for (int half = 0; half < 2; half++) {
            const int row = m0 + (wm << 6) + (mf << 4) + quad + (half << 3);
            const float xxr = g_xx[row];
            ull   k1 = 0ull;
            float s1 = -3.0e38f, s2 = -3.0e38f;
#pragma unroll
            for (int nf = 0; nf < 4; nf++) {
                const int col = j0 + (wn << 5) + (nf << 3) + (q << 1);
                float c0 = acc[mf][nf][half << 1];
                float c1 = acc[mf][nf][(half << 1) + 1];
                float2 g2 = *(const float2*)(G + (size_t)row * KCODES + col);
                float2 e2 = *(const float2*)(g_ee + col);

                float d0 = (xxr + e2.x) - 2.0f * c0;
                float d1 = (xxr + e2.y) - 2.0f * c1;
                if (d0 < 85.0f) {
                    float pr = 1.0f / (1.0f + expf(d0));
                    kld += pr * logf(fmaxf(pr, 1e-8f));
                }
                if (d1 < 85.0f) {
                    float pr = 1.0f / (1.0f + expf(d1));
                    kld += pr * logf(fmaxf(pr, 1e-8f));
                }
                float s0 = g2.x - d0;
                float s1v = g2.y - d1;
                ull k0 = packKey(s0, col);
                if (k0 > k1) { s2 = s1; k1 = k0; s1 = s0; } else { s2 = fmaxf(s2, s0); }
                ull kk1 = packKey(s1v, col + 1);
                if (kk1 > k1) { s2 = s1; k1 = kk1; s1 = s1v; } else { s2 = fmaxf(s2, s1v); }

                *(float2*)(enc + (size_t)row * KCODES + col) = z2;
            }
#pragma unroll
            for (int x = 1; x <= 2; x <<= 1) {
                ull   ok  = __shfl_xor_sync(0xFFFFFFFFu, k1, x);
                float os1 = __shfl_xor_sync(0xFFFFFFFFu, s1, x);
                float os2 = __shfl_xor_sync(0xFFFFFFFFu, s2, x);
                if (ok > k1) { s2 = fmaxf(fmaxf(s2, os2), s1); k1 = ok; s1 = os1; }
                else         { s2 = fmaxf(fmaxf(s2, os2), os1); }
            }
            if (q == 0) {
                int slot = (row << 5) + ((int)blockIdx.x << 2) + wn;
                g_pKey[slot] = k1;
                g_pS2[slot]  = s2;
            }
        }
    }

#pragma unroll
    for (int off = 16; off; off >>= 1) kld += __shfl_down_sync(0xFFFFFFFFu, kld, off);
    if (lane == 0 && kld != 0.0f) atomicAdd(&g_kldSum, kld);
}

// ---------------- merge partials -> idx or rescue flag ----------------
__global__ void mergeKernel() {
    int row = blockIdx.x * blockDim.x + threadIdx.x;
    if (row >= N_ROWS) return;
    ull best = 0ull;
#pragma unroll
    for (int t = 0; t < 32; t++) best = max(best, g_pKey[(row << 5) + t]);
    float runner = -3.0e38f;
#pragma unroll
    for (int t = 0; t < 32; t++) {
        ull k = g_pKey[(row << 5) + t];
        if (k != best) runner = fmaxf(runner, decodeKey(k));
        runner = fmaxf(runner, g_pS2[(row << 5) + t]);
    }
    float margin = decodeKey(best) - runner;
    if (margin < DELTA) {
        int p = atomicAdd(&g_nRescue, 1);
        g_rescueRows[p] = row;
    } else {
        g_rowIdx[row] = 1023 - (int)(unsigned)(best & 0xFFFFFFFFull);
    }
}

// ------- fp32 rescue, 8 rows per block share one sweep of E ----------
#define BR 8
__global__ __launch_bounds__(256)
void rescueKernel(const float* __restrict__ in, const float* __restrict__ E,
                  const float* __restrict__ G) {
    __shared__ float sx[BR][CDIM];
    __shared__ int   srow[BR];
    __shared__ ull   rk[8];
    const int tid = threadIdx.x;
    const int nR  = g_nRescue;
    for (int base = blockIdx.x * BR; base < nR; base += gridDim.x * BR) {
        const int nb = min(BR, nR - base);
        for (int r = 0; r < nb; r++) {
            int row = g_rescueRows[base + r];
            if (tid == 0) srow[r] = row;
            sx[r][tid] = in[(size_t)(row >> 10) * CDIM * HWDIM
                            + (size_t)tid * HWDIM + (row & 1023)];
        }
        __syncthreads();

        ull key[BR];
#pragma unroll
        for (int r = 0; r < BR; r++) key[r] = 0ull;

#pragma unroll 1
        for (int cc = 0; cc < 4; cc++) {
            int code = tid + (cc << 8);
            const float* e = E + (size_t)code * CDIM;
            float acc[BR];
#pragma unroll
            for (int r = 0; r < BR; r++) acc[r] = 0.0f;
#pragma unroll 4
            for (int k = 0; k < CDIM; k++) {
                float ek = e[k];
#pragma unroll
                for (int r = 0; r < BR; r++) acc[r] = fmaf(sx[r][k], ek, acc[r]);
            }
            float ee = g_ee[code];
            for (int r = 0; r < nb; r++) {
                int row = srow[r];
                float d = (g_xx[row] + ee) - 2.0f * acc[r];
                float s = G[(size_t)row * KCODES + code] - d;
                ull kk = packKey(s, code);
                key[r] = max(key[r], kk);
            }
        }
        for (int r = 0; r < nb; r++) {
            ull k = key[r];
#pragma unroll
            for (int off = 16; off; off >>= 1)
                k = max(k, __shfl_down_sync(0xFFFFFFFFu, k, off));
            if ((tid & 31) == 0) rk[tid >> 5] = k;
            __syncthreads();
            if (tid == 0) {
                ull b2 = rk[0];
#pragma unroll
                for (int w = 1; w < 8; w++) b2 = max(b2, rk[w]);
                g_rowIdx[srow[r]] = 1023 - (int)(unsigned)(b2 & 0xFFFFFFFFull);
            }
            __syncthreads();
        }
    }
}

// ---------------- finish: one-hot scatter, quantized NCHW, histogram ----------
__global__ __launch_bounds__(256)
void finishKernel(const float* __restrict__ E, float* __restrict__ out) {
    __shared__ int   sIdx[32];
    __shared__ float sQ[32 * 257];

    const int n0  = blockIdx.x << 5;
    const int tid = threadIdx.x;

    if (tid < 32) {
        int idx = g_rowIdx[n0 + tid];
        sIdx[tid] = idx;
        out[ENC_OFF + (size_t)(n0 + tid) * KCODES + idx] = 1.0f;
        atomicAdd(&g_counts[idx], 1u);
    }
    __syncthreads();

    const int c = tid;
#pragma unroll 4
    for (int i = 0; i < 32; i++)
        sQ[i * 257 + c] = E[(size_t)sIdx[i] * CDIM + c];
    __syncthreads();

    const int b   = n0 >> 10;
    const int hw0 = n0 & 1023;
    float* qb = out + QUANT_OFF + (size_t)b * CDIM * HWDIM;
#pragma unroll 4
    for (int it = 0; it < 32; it++) {
        int f  = it * 256 + tid;
        int cc = f >> 5;
        int ii = f & 31;
        qb[(size_t)cc * HWDIM + hw0 + ii] = sQ[ii * 257 + cc];
    }
}

// ---------------- scalars ----------------
// loss = C*(kld + e_lat*stopgrad(kld/clip(e_lat,1e-8))); e_lat >> 1e-8 always,
// so ratio == 1 exactly and loss = 3*kld (e_latent drops out).
__global__ void lossKernel(float* __restrict__ out) {
    __shared__ float red[32];
    int t = threadIdx.x;
    float avg  = (float)g_counts[t] * (1.0f / 32768.0f);
    float term = avg * logf(avg + 1e-10f);
#pragma unroll
    for (int off = 16; off; off >>= 1) term += __shfl_down_sync(0xFFFFFFFFu, term, off);
    if ((t & 31) == 0) red[t >> 5] = term;
    __syncthreads();
    if (t < 32) {
        float v = red[t];
#pragma unroll
        for (int off = 16; off; off >>= 1) v += __shfl_down_sync(0xFFFFFFFFu, v, off);
        if (t == 0) {
            float kld = g_kldSum * (1.0f / 32768.0f);
            out[0]        = 3.0f * kld;
            out[PERP_OFF] = expf(-v);
        }
    }
}

// ---------------- launch ----------------
extern "C" void kernel_launch(void* const* d_in, const int* in_sizes, int n_in,
                              void* d_out, int out_size) {
    const float* inp = (const float*)d_in[0];
    const float* emb = (const float*)d_in[1];
    const float* gum = (const float*)d_in[2];
    float* out = (float*)d_out;
    float* enc = out + ENC_OFF;

    cudaFuncSetAttribute(gemmKernel, cudaFuncAttributeMaxDynamicSharedMemorySize, SMEM_DYN);

    initKernel<<<128, 256>>>();
    transConvKernel<<<dim3(32, 8, 32), dim3(32, 8)>>>(inp);
    sumsqEConv<<<128, 256>>>(emb);
    gemmKernel<<<dim3(KCODES / 128, N_ROWS / 128), 256, SMEM_DYN>>>(gum, enc);
    mergeKernel<<<128, 256>>>();
    rescueKernel<<<256, 256>>>(inp, emb, gum);
    finishKernel<<<N_ROWS / 32, 256>>>(emb, out);
    lossKernel<<<1, 1024>>>(out);
}

// round 10
// speedup vs baseline: 1.6369x; 1.1116x over previous
#include <cuda_runtime.h>
#include <cuda_fp16.h>
#include <cstdint>

typedef unsigned long long ull;

#define CDIM    256
#define HWDIM   1024
#define N_ROWS  32768
#define KCODES  1024

#define QUANT_OFF 1
#define PERP_OFF  8388609
#define ENC_OFF   8388610

#define DELTA   0.06f

// ---------------- scratch ----------------
__device__ __half         g_Xh[N_ROWS * CDIM];
__device__ __half         g_Eh[KCODES * CDIM];
__device__ float          g_xx[N_ROWS];
__device__ float          g_ee[KCODES];
__device__ ull            g_pKey[N_ROWS * 32];  // per (row, 32-col segment) top1
__device__ float          g_pS2[N_ROWS * 32];   // per-segment runner-up score
__device__ int            g_rowIdx[N_ROWS];
__device__ int            g_rescueRows[N_ROWS];
__device__ int            g_nRescue;
__device__ unsigned int   g_counts[KCODES];
__device__ float          g_kldSum;

// ---------------- helpers ----------------
__device__ __forceinline__ uint32_t smem_u32(const void* p) {
    uint32_t a;
    asm("{ .reg .u64 t; cvta.to.shared.u64 t, %1; cvt.u32.u64 %0, t; }" : "=r"(a) : "l"(p));
    return a;
}
__device__ __forceinline__ void cp16(uint32_t dst, const void* src) {
    asm volatile("cp.async.cg.shared.global [%0], [%1], 16;" :: "r"(dst), "l"(src));
}
#define CP_COMMIT() asm volatile("cp.async.commit_group;" ::: "memory")
#define CP_WAIT1()  asm volatile("cp.async.wait_group 1;" ::: "memory")
#define CP_WAIT0()  asm volatile("cp.async.wait_group 0;" ::: "memory")

__device__ __forceinline__ void ldsm4(uint32_t* r, uint32_t a) {
    asm volatile("ldmatrix.sync.aligned.m8n8.x4.shared.b16 {%0,%1,%2,%3}, [%4];"
                 : "=r"(r[0]), "=r"(r[1]), "=r"(r[2]), "=r"(r[3]) : "r"(a));
}
__device__ __forceinline__ void mma_f16(float* c, uint32_t a0, uint32_t a1,
                                        uint32_t a2, uint32_t a3,
                                        uint32_t b0, uint32_t b1) {
    asm volatile("mma.sync.aligned.m16n8k16.row.col.f32.f16.f16.f32 "
                 "{%0,%1,%2,%3}, {%4,%5,%6,%7}, {%8,%9}, {%0,%1,%2,%3};"
                 : "+f"(c[0]), "+f"(c[1]), "+f"(c[2]), "+f"(c[3])
                 : "r"(a0), "r"(a1), "r"(a2), "r"(a3), "r"(b0), "r"(b1));
}

__device__ __forceinline__ ull packKey(float s, int idx) {
    unsigned u = __float_as_uint(s);
    u = (u & 0x80000000u) ? ~u : (u | 0x80000000u);
    return ((ull)u << 32) | (unsigned)(1023 - idx);
}
__device__ __forceinline__ float decodeKey(ull k) {
    unsigned u = (unsigned)(k >> 32);
    unsigned v = (u & 0x80000000u) ? (u & 0x7FFFFFFFu) : ~u;
    return __uint_as_float(v);
}

// ---------------- init ----------------
__global__ void initKernel() {
    int t = blockIdx.x * blockDim.x + threadIdx.x;
    if (t < N_ROWS) g_xx[t] = 0.0f;
    if (t < KCODES) g_counts[t] = 0u;
    if (t == 0) { g_kldSum = 0.0f; g_nRescue = 0; }
}

// ------- NCHW -> [N,C] fp16 + fused ||x||^2 ----------
__global__ void transConvKernel(const float* __restrict__ in) {
    __shared__ float tile[32][33];
    int b   = blockIdx.z;
    int hw0 = blockIdx.x << 5;
    int c0  = blockIdx.y << 5;
    const float* p = in + (size_t)b * CDIM * HWDIM;
#pragma unroll
    for (int j = 0; j < 4; j++) {
        int cl = threadIdx.y + (j << 3);
        tile[cl][threadIdx.x] = p[(size_t)(c0 + cl) * HWDIM + hw0 + threadIdx.x];
    }
    __syncthreads();
#pragma unroll
    for (int j = 0; j < 4; j++) {
        int hwl = threadIdx.y + (j << 3);
        int row = b * HWDIM + hw0 + hwl;
        size_t o = (size_t)row * CDIM + c0 + threadIdx.x;
        float v = tile[threadIdx.x][hwl];
        g_Xh[o] = __float2half_rn(v);
        float s = v * v;
#pragma unroll
        for (int off = 16; off; off >>= 1) s += __shfl_xor_sync(0xFFFFFFFFu, s, off);
        if (threadIdx.x == 0) atomicAdd(&g_xx[row], s);
    }
}

// ---------------- E: sum-of-squares + fp16 convert ----------------
__global__ void sumsqEConv(const float* __restrict__ E) {
    int gw   = (blockIdx.x * blockDim.x + threadIdx.x) >> 5;
    int lane = threadIdx.x & 31;
    if (gw >= KCODES) return;
    const float* p = E + (size_t)gw * CDIM;
    float4 a = *(const float4*)(p + (lane << 2));
    float4 b = *(const float4*)(p + 128 + (lane << 2));
    float s = a.x*a.x + a.y*a.y + a.z*a.z + a.w*a.w
            + b.x*b.x + b.y*b.y + b.z*b.z + b.w*b.w;
#pragma unroll
    for (int off = 16; off; off >>= 1) s += __shfl_xor_sync(0xFFFFFFFFu, s, off);
    if (lane == 0) g_ee[gw] = s;

    float va[8] = { a.x, a.y, a.z, a.w, b.x, b.y, b.z, b.w };
#pragma unroll
    for (int i = 0; i < 8; i++) {
        size_t o = (size_t)gw * CDIM + ((i < 4) ? (lane << 2) + i : 128 + (lane << 2) + i - 4);
        g_Eh[o] = __float2half_rn(va[i]);
    }
}

// ---------------- HMMA fp16 1-term GEMM (K=256) + fused epilogue -------
// CTA: 128 rows x 128 codes, 8 warps (2x4), warp 64x32. 4 K-chunks of 64.
// A: 128x256 fp16, resident, 512B rows XOR-swizzled. B: 3-stage ring, 128x64.
#define A_BYTES  65536
#define B_BYTES  16384
#define SMEM_DYN (A_BYTES + 3 * B_BYTES)   // 114688; 2 CTAs/SM
__global__ __launch_bounds__(256, 2)
void gemmKernel(const float* __restrict__ G, float* __restrict__ enc) {
    extern __shared__ char dsm[];
    const uint32_t sb = smem_u32(dsm);

    const int tid  = threadIdx.x;
    const int warp = tid >> 5;
    const int lane = tid & 31;
    const int wm   = warp >> 2;          // 0..1
    const int wn   = warp & 3;           // 0..3
    const int m0   = blockIdx.y << 7;
    const int j0   = blockIdx.x << 7;

    float acc[4][4][4];
#pragma unroll
    for (int i = 0; i < 4; i++)
#pragma unroll
        for (int j = 0; j < 4; j++)
#pragma unroll
            for (int k = 0; k < 4; k++) acc[i][j][k] = 0.0f;

    // ---- A: load all 128x256 fp16, swizzled, one cp.async group ----
#pragma unroll
    for (int t = 0; t < 16; t++) {
        int id = tid + (t << 8);
        int r = id >> 5, k16 = id & 31;
        uint32_t sw = (uint32_t)((k16 & 24) | ((k16 ^ r) & 7));
        cp16(sb + (uint32_t)r * 512u + (sw << 4),
             g_Xh + (size_t)(m0 + r) * CDIM + (k16 << 3));
    }
    CP_COMMIT();

    auto loadB = [&](int c) {
        const int kb = c << 6;
        const uint32_t bBase = sb + A_BYTES + (uint32_t)(c % 3) * B_BYTES;
#pragma unroll
        for (int t = 0; t < 4; t++) {
            int id = tid + (t << 8);
            int r = id >> 3, k16 = id & 7;
            cp16(bBase + (uint32_t)r * 128u + (uint32_t)((k16 ^ (r & 7)) << 4),
                 g_Eh + (size_t)(j0 + r) * CDIM + kb + (k16 << 3));
        }
        CP_COMMIT();
    };

    loadB(0);
    loadB(1);

#pragma unroll 1
    for (int c = 0; c < 4; c++) {
        if (c < 3) { CP_WAIT1(); } else { CP_WAIT0(); }
        __syncthreads();
        if (c + 2 < 4) loadB(c + 2);

        const uint32_t bBase = sb + A_BYTES + (uint32_t)(c % 3) * B_BYTES;
#pragma unroll
        for (int ks = 0; ks < 4; ks++) {
            uint32_t bfr[4][2];
#pragma unroll
            for (int nfp = 0; nfp < 2; nfp++) {
                int g = lane >> 3;                    // 0..3
                int rowb = (wn << 5) + (nfp << 4) + ((g >> 1) << 3) + (lane & 7);
                int k16 = (ks << 1) + (g & 1);
                uint32_t addr = bBase + (uint32_t)rowb * 128u
                              + (uint32_t)((k16 ^ (rowb & 7)) << 4);
                uint32_t r4[4];
                ldsm4(r4, addr);
                bfr[(nfp << 1) + 0][0] = r4[0];
                bfr[(nfp << 1) + 0][1] = r4[1];
                bfr[(nfp << 1) + 1][0] = r4[2];
                bfr[(nfp << 1) + 1][1] = r4[3];
            }
#pragma unroll
            for (int mf = 0; mf < 4; mf++) {
                int rowa = (wm << 6) + (mf << 4) + (lane & 15);
                int k16  = (c << 3) + (ks << 1) + (lane >> 4);
                uint32_t sw = (uint32_t)((k16 & 24) | ((k16 ^ rowa) & 7));
                uint32_t afr[4];
                ldsm4(afr, sb + (uint32_t)rowa * 512u + (sw << 4));
#pragma unroll
                for (int nf = 0; nf < 4; nf++)
                    mma_f16(acc[mf][nf], afr[0], afr[1], afr[2], afr[3],
                            bfr[nf][0], bfr[nf][1]);
            }
        }
    }
    __syncthreads();

    // -------- epilogue: fragment c0=(r,2q) c1=(r,2q+1) c2/c3=(r+8,..) --------
    const int quad = lane >> 2;
    const int q    = lane & 3;
    float kld = 0.0f;
    const float2 z2 = make_float2(0.f, 0.f);

#pragma unroll
    for (int mf = 0; mf < 4; mf++) {
#pragma unroll
        for (int half = 0; half < 2; half++) {
            const int row = m0 + (wm << 6) + (mf << 4) + quad + (half << 3);
            const float xxr = g_xx[row];
            ull   k1 = 0ull;
            float s1 = -3.0e38f, s2 = -3.0e38f;
#pragma unroll
            for (int nf = 0; nf < 4; nf++) {
                const int col = j0 + (wn << 5) + (nf << 3) + (q << 1);
                float c0 = acc[mf][nf][half << 1];
                float c1 = acc[mf][nf][(half << 1) + 1];
                float2 g2 = *(const float2*)(G + (size_t)row * KCODES + col);
                float2 e2 = *(const float2*)(g_ee + col);

                float d0 = (xxr + e2.x) - 2.0f * c0;
                float d1 = (xxr + e2.y) - 2.0f * c1;
                if (d0 < 85.0f) {
                    float pr = 1.0f / (1.0f + expf(d0));
                    kld += pr * logf(fmaxf(pr, 1e-8f));
                }
                if (d1 < 85.0f) {
                    float pr = 1.0f / (1.0f + expf(d1));
                    kld += pr * logf(fmaxf(pr, 1e-8f));
                }
                float s0 = g2.x - d0;
                float s1v = g2.y - d1;
                ull k0 = packKey(s0, col);
                if (k0 > k1) { s2 = s1; k1 = k0; s1 = s0; } else { s2 = fmaxf(s2, s0); }
                ull kk1 = packKey(s1v, col + 1);
                if (kk1 > k1) { s2 = s1; k1 = kk1; s1 = s1v; } else { s2 = fmaxf(s2, s1v); }

                *(float2*)(enc + (size_t)row * KCODES + col) = z2;
            }
#pragma unroll
            for (int x = 1; x <= 2; x <<= 1) {
                ull   ok  = __shfl_xor_sync(0xFFFFFFFFu, k1, x);
                float os1 = __shfl_xor_sync(0xFFFFFFFFu, s1, x);
                float os2 = __shfl_xor_sync(0xFFFFFFFFu, s2, x);
                if (ok > k1) { s2 = fmaxf(fmaxf(s2, os2), s1); k1 = ok; s1 = os1; }
                else         { s2 = fmaxf(fmaxf(s2, os2), os1); }
            }
            if (q == 0) {
                int slot = (row << 5) + ((int)blockIdx.x << 2) + wn;
                g_pKey[slot] = k1;
                g_pS2[slot]  = s2;
            }
        }
    }

#pragma unroll
    for (int off = 16; off; off >>= 1) kld += __shfl_down_sync(0xFFFFFFFFu, kld, off);
    if (lane == 0 && kld != 0.0f) atomicAdd(&g_kldSum, kld);
}

// ------- argmax: warp per row; exact fp32 re-check of near-top candidates ----
__global__ __launch_bounds__(256)
void argmaxKernel(const float* __restrict__ in, const float* __restrict__ E,
                  const float* __restrict__ G) {
    const int wid  = threadIdx.x >> 5;
    const int lane = threadIdx.x & 31;
    const int row  = (blockIdx.x << 3) + wid;
    const unsigned FULL = 0xFFFFFFFFu;

    ull   pk  = g_pKey[(row << 5) + lane];
    float ps2 = g_pS2[(row << 5) + lane];

    ull best = pk;
#pragma unroll
    for (int off = 16; off; off >>= 1) best = max(best, __shfl_xor_sync(FULL, best, off));
    float sbest = decodeKey(best);
    float sc    = decodeKey(pk);
    float oth   = (pk == best) ? ps2 : fmaxf(sc, ps2);
#pragma unroll
    for (int off = 16; off; off >>= 1) oth = fmaxf(oth, __shfl_xor_sync(FULL, oth, off));

    if (sbest - oth >= DELTA) {   // warp-uniform
        if (lane == 0) g_rowIdx[row] = 1023 - (int)(unsigned)(best & 0xFFFFFFFFull);
        return;
    }
    // ambiguous: if any segment runner-up is also near the top, a 3rd-place
    // true winner could hide behind it -> rare full-row fallback
    if (__any_sync(FULL, ps2 >= sbest - DELTA)) {
        if (lane == 0) {
            int p = atomicAdd(&g_nRescue, 1);
            g_rescueRows[p] = row;
        }
        return;
    }
    // exact fp32 re-check of segment winners within DELTA of approx top
    const int b  = row >> 10;
    const int hw = row & 1023;
    const float* xp = in + (size_t)b * CDIM * HWDIM + hw;
    float xr[8];
#pragma unroll
    for (int j = 0; j < 8; j++)
        xr[j] = xp[(size_t)((lane << 3) + j) * HWDIM];
    const float xxr = g_xx[row];

    unsigned cm = __ballot_sync(FULL, sc >= sbest - DELTA);
    ull bestExact = 0ull;
    while (cm) {
        int src = __ffs(cm) - 1;
        cm &= cm - 1;
        ull ck = __shfl_sync(FULL, pk, src);
        int idx = 1023 - (int)(unsigned)(ck & 0xFFFFFFFFull);
        const float* e = E + (size_t)idx * CDIM + (lane << 3);
        float dot = 0.0f;
#pragma unroll
        for (int j = 0; j < 8; j++) dot = fmaf(xr[j], e[j], dot);
#pragma unroll
        for (int off = 16; off; off >>= 1) dot += __shfl_xor_sync(FULL, dot, off);
        float d = (xxr + g_ee[idx]) - 2.0f * dot;
        float s = G[(size_t)row * KCODES + idx] - d;
        bestExact = max(bestExact, packKey(s, idx));
    }
    if (lane == 0) g_rowIdx[row] = 1023 - (int)(unsigned)(bestExact & 0xFFFFFFFFull);
}

// ------- fp32 full-row rescue (rare fallback), 8 rows share one E sweep ------
#define BR 8
__global__ __launch_bounds__(256)
void rescueKernel(const float* __restrict__ in, const float* __restrict__ E,
                  const float* __restrict__ G) {
    __shared__ float sx[BR][CDIM];
    __shared__ int   srow[BR];
    __shared__ ull   rk[8];
    const int tid = threadIdx.x;
    const int nR  = g_nRescue;
    for (int base = blockIdx.x * BR; base < nR; base += gridDim.x * BR) {
        const int nb = min(BR, nR - base);
        for (int r = 0; r < nb; r++) {
            int row = g_rescueRows[base + r];
            if (tid == 0) srow[r] = row;
            sx[r][tid] = in[(size_t)(row >> 10) * CDIM * HWDIM
                            + (size_t)tid * HWDIM + (row & 1023)];
        }
        __syncthreads();

        ull key[BR];
#pragma unroll
        for (int r = 0; r < BR; r++) key[r] = 0ull;

#pragma unroll 1
        for (int cc = 0; cc < 4; cc++) {
            int code = tid + (cc << 8);
            const float* e = E + (size_t)code * CDIM;
            float acc[BR];
#pragma unroll
            for (int r = 0; r < BR; r++) acc[r] = 0.0f;
#pragma unroll 4
            for (int k = 0; k < CDIM; k++) {
                float ek = e[k];
#pragma unroll
                for (int r = 0; r < BR; r++) acc[r] = fmaf(sx[r][k], ek, acc[r]);
            }
            float ee = g_ee[code];
            for (int r = 0; r < nb; r++) {
                int row = srow[r];
                float d = (g_xx[row] + ee) - 2.0f * acc[r];
                float s = G[(size_t)row * KCODES + code] - d;
                key[r] = max(key[r], packKey(s, code));
            }
        }
        for (int r = 0; r < nb; r++) {
            ull k = key[r];
#pragma unroll
            for (int off = 16; off; off >>= 1)
                k = max(k, __shfl_down_sync(0xFFFFFFFFu, k, off));
            if ((tid & 31) == 0) rk[tid >> 5] = k;
            __syncthreads();
            if (tid == 0) {
                ull b2 = rk[0];
#pragma unroll
                for (int w = 1; w < 8; w++) b2 = max(b2, rk[w]);
                g_rowIdx[srow[r]] = 1023 - (int)(unsigned)(b2 & 0xFFFFFFFFull);
            }
            __syncthreads();
        }
    }
}

// ---------------- finish: one-hot scatter, quantized NCHW, histogram ----------
__global__ __launch_bounds__(256)
void finishKernel(const float* __restrict__ E, float* __restrict__ out) {
    __shared__ int   sIdx[32];
    __shared__ float sQ[32 * 257];

    const int n0  = blockIdx.x << 5;
    const int tid = threadIdx.x;

    if (tid < 32) {
        int idx = g_rowIdx[n0 + tid];
        sIdx[tid] = idx;
        out[ENC_OFF + (size_t)(n0 + tid) * KCODES + idx] = 1.0f;
        atomicAdd(&g_counts[idx], 1u);
    }
    __syncthreads();

    const int c = tid;
#pragma unroll 4
    for (int i = 0; i < 32; i++)
        sQ[i * 257 + c] = E[(size_t)sIdx[i] * CDIM + c];
    __syncthreads();

    const int b   = n0 >> 10;
    const int hw0 = n0 & 1023;
    float* qb = out + QUANT_OFF + (size_t)b * CDIM * HWDIM;
#pragma unroll 4
    for (int it = 0; it < 32; it++) {
        int f  = it * 256 + tid;
        int cc = f >> 5;
        int ii = f & 31;
        qb[(size_t)cc * HWDIM + hw0 + ii] = sQ[ii * 257 + cc];
    }
}

// ---------------- scalars ----------------
// loss = C*(kld + e_lat*stopgrad(kld/clip(e_lat,1e-8))); e_lat >> 1e-8 always,
// so ratio == 1 exactly and loss = 3*kld (e_latent drops out).
__global__ void lossKernel(float* __restrict__ out) {
    __shared__ float red[32];
    int t = threadIdx.x;
    float avg  = (float)g_counts[t] * (1.0f / 32768.0f);
    float term = avg * logf(avg + 1e-10f);
#pragma unroll
    for (int off = 16; off; off >>= 1) term += __shfl_down_sync(0xFFFFFFFFu, term, off);
    if ((t & 31) == 0) red[t >> 5] = term;
    __syncthreads();
    if (t < 32) {
        float v = red[t];
#pragma unroll
        for (int off = 16; off; off >>= 1) v += __shfl_down_sync(0xFFFFFFFFu, v, off);
        if (t == 0) {
            float kld = g_kldSum * (1.0f / 32768.0f);
            out[0]        = 3.0f * kld;
            out[PERP_OFF] = expf(-v);
        }
    }
}

// ---------------- launch ----------------
extern "C" void kernel_launch(void* const* d_in, const int* in_sizes, int n_in,
                              void* d_out, int out_size) {
    const float* inp = (const float*)d_in[0];
    const float* emb = (const float*)d_in[1];
    const float* gum = (const float*)d_in[2];
    float* out = (float*)d_out;
    float* enc = out + ENC_OFF;

    cudaFuncSetAttribute(gemmKernel, cudaFuncAttributeMaxDynamicSharedMemorySize, SMEM_DYN);

    initKernel<<<128, 256>>>();
    transConvKernel<<<dim3(32, 8, 32), dim3(32, 8)>>>(inp);
    sumsqEConv<<<128, 256>>>(emb);
    gemmKernel<<<dim3(KCODES / 128, N_ROWS / 128), 256, SMEM_DYN>>>(gum, enc);
    argmaxKernel<<<N_ROWS / 8, 256>>>(inp, emb, gum);
    rescueKernel<<<256, 256>>>(inp, emb, gum);
    finishKernel<<<N_ROWS / 32, 256>>>(emb, out);
    lossKernel<<<1, 1024>>>(out);
}